// round 8
// baseline (speedup 1.0000x reference)
#include <cuda_runtime.h>
#include <cuda_bf16.h>
#include <math.h>
#include <stdint.h>

// ---------------------------------------------------------------------------
// KAN feedforward via int8 mma.sync (m16n8k32, 2x MAC rate) with 2-term
// per-row int8 split:
//   v = s*q1 + (s/254)*q2,  |q| <= 127
//   A.B = sA*sB*[ q1a.q1b  +  (q1a.q2b + q2a.q1b)/254 ]   (drop q2.q2 ~ 2e-10)
// Exact s32 accumulation; 3 slab-terms per GEMM combined by a scaling kernel.
// F stored [q1 | q2] (2K int8), W same; chunk remap selects term pairs.
// ---------------------------------------------------------------------------

#define D_MODEL 512
#define HIDDEN  1024
#define NFEAT   9
#define NTOK    4096
#define K1      (D_MODEL * NFEAT)   // 4608
#define K2      (HIDDEN  * NFEAT)   // 9216
#define INV254  (1.0f / 254.0f)

__device__ int8_t g_F  [(size_t)NTOK * 2 * K2];        // 75.5 MB
__device__ int8_t g_W1 [(size_t)HIDDEN * 2 * K1];      // 9.4 MB
__device__ int8_t g_W2 [(size_t)D_MODEL * 2 * K2];     // 9.4 MB
__device__ int    g_S  [(size_t)12 * NTOK * D_MODEL];  // 96 MB? no: 12*4096*512 = 25.2M ints = 100MB... see note
__device__ float  g_h  [(size_t)NTOK * HIDDEN];        // 16 MB
__device__ float  g_sF [NTOK];
__device__ float  g_sW1[HIDDEN];
__device__ float  g_sW2[D_MODEL];
// note: layer1 needs 3*N*H = 12.6M ints, layer2 needs 6*N*D = 12.6M ints;
// g_S sized 12*N*D = 25.2M ints (= 3*N*H since H = 2*D) -- covers both.

// ---------------------------------------------------------------------------
// Helpers
// ---------------------------------------------------------------------------
__device__ __forceinline__ uint32_t smem_u32(const void* p) {
    uint32_t a;
    asm("{ .reg .u64 t; cvta.to.shared.u64 t, %1; cvt.u32.u64 %0, t; }"
        : "=r"(a) : "l"(p));
    return a;
}

__device__ __forceinline__ uint32_t lds_addr(uint32_t base, int row, int col16) {
    return base + row * 128 + ((col16 ^ (row & 7)) << 4);
}

#define CP_ASYNC16(sm, gm)                                                    \
    asm volatile("cp.async.cg.shared.global [%0], [%1], 16;"                  \
                 :: "r"(sm), "l"(gm) : "memory")
#define CP_COMMIT()  asm volatile("cp.async.commit_group;" ::: "memory")
#define CP_WAIT1()   asm volatile("cp.async.wait_group 1;" ::: "memory")

__device__ __forceinline__ void ldsm_x4(uint32_t r[4], uint32_t addr) {
    asm volatile("ldmatrix.sync.aligned.m8n8.x4.shared.b16 {%0,%1,%2,%3}, [%4];"
                 : "=r"(r[0]), "=r"(r[1]), "=r"(r[2]), "=r"(r[3]) : "r"(addr));
}

// int8 MMA: m16n8k32, s32 accumulate (exact)
__device__ __forceinline__ void mma16832s8(int c[4], const uint32_t a[4],
                                           const uint32_t b[2]) {
    asm volatile(
        "mma.sync.aligned.m16n8k32.row.col.s32.s8.s8.s32 "
        "{%0,%1,%2,%3}, {%4,%5,%6,%7}, {%8,%9}, {%0,%1,%2,%3};"
        : "+r"(c[0]), "+r"(c[1]), "+r"(c[2]), "+r"(c[3])
        : "r"(a[0]), "r"(a[1]), "r"(a[2]), "r"(a[3]), "r"(b[0]), "r"(b[1]));
}

// ---------------------------------------------------------------------------
// Spline features (validated R3-R7)
// ---------------------------------------------------------------------------
__device__ __forceinline__ float knotf(int k) {
    return __fadd_rn(__fmul_rn((float)(k - 3), 0.4f), -1.0f);
}

__device__ __forceinline__ void kan_features(float x, float f[NFEAT]) {
    float sig = 1.0f / (1.0f + expf(-x));
    f[0] = x * sig;
#pragma unroll
    for (int g = 0; g < 8; g++) f[1 + g] = 0.0f;

    float u = (x - knotf(0)) * 2.5f;
    if (u > 16.0f) u = 16.0f;
    if (u < -16.0f) u = -16.0f;
    int j = (int)floorf(u);
    if (j < -1) j = -1;
    if (j > 11) j = 11;
    if (x < knotf(j))            j -= 1;
    else if (x >= knotf(j + 1))  j += 1;
    if (j < 0 || j > 10) return;

    float s  = (x - knotf(j)) * 2.5f;
    float s2 = s * s, s3 = s2 * s;
    float om = 1.0f - s;
    float w0 = om * om * om * (1.0f / 6.0f);
    float w1 = (3.0f * s3 - 6.0f * s2 + 4.0f) * (1.0f / 6.0f);
    float w2 = (-3.0f * s3 + 3.0f * s2 + 3.0f * s + 1.0f) * (1.0f / 6.0f);
    float w3 = s3 * (1.0f / 6.0f);
    float w[4] = {w0, w1, w2, w3};
    int g0 = j - 3;
#pragma unroll
    for (int r = 0; r < 4; r++) {
        int g = g0 + r;
        if (g >= 0 && g < 8) f[1 + g] = w[r];
    }
}

__device__ __forceinline__ void quant2(float v, float s1, float inv1, float inv2,
                                       int8_t* o1, int8_t* o2) {
    int q1 = __float2int_rn(v * inv1);
    float r = fmaf((float)(-q1), s1, v);
    int q2 = __float2int_rn(r * inv2);
    q2 = max(-127, min(127, q2));
    *o1 = (int8_t)q1;
    *o2 = (int8_t)q2;
}

// ---------------------------------------------------------------------------
// Feature expand + per-token int8 quantize. Block = one token, 256 threads.
//   Fq[n][2K] = [q1 | q2],  sF[n] = scale
// maxf = max(2/3, max|silu|)  (spline basis values are <= 2/3)
// ---------------------------------------------------------------------------
__global__ __launch_bounds__(256)
void build_features_q8(const float* __restrict__ X, int8_t* __restrict__ Fq,
                       float* __restrict__ sF, int I) {
    __shared__ float red[256];
    __shared__ __align__(16) int8_t s1b[1024 * NFEAT];
    __shared__ __align__(16) int8_t s2b[1024 * NFEAT];
    const int n = blockIdx.x;
    const int t = threadIdx.x;
    const int ipt = I >> 8;
    const int K = I * NFEAT;

    float xs[4];
    float lmax = 0.66666667f;
#pragma unroll
    for (int r = 0; r < 4; r++) {
        if (r < ipt) {
            float x = X[(size_t)n * I + t + (r << 8)];
            xs[r] = x;
            float sl = x / (1.0f + expf(-x));
            lmax = fmaxf(lmax, fabsf(sl));
        }
    }
    red[t] = lmax;
    __syncthreads();
    for (int off = 128; off > 0; off >>= 1) {
        if (t < off) red[t] = fmaxf(red[t], red[t + off]);
        __syncthreads();
    }
    const float maxf = red[0];
    const float s1   = maxf * (1.0f / 127.0f);
    const float inv1 = 127.0f / maxf;
    const float inv2 = inv1 * 254.0f;

#pragma unroll
    for (int r = 0; r < 4; r++) {
        if (r < ipt) {
            int i = t + (r << 8);
            float f[NFEAT];
            kan_features(xs[r], f);
#pragma unroll
            for (int fi = 0; fi < NFEAT; fi++)
                quant2(f[fi], s1, inv1, inv2,
                       &s1b[i * NFEAT + fi], &s2b[i * NFEAT + fi]);
        }
    }
    __syncthreads();

    const int words = (I * NFEAT) >> 2;
    const uint32_t* w1 = reinterpret_cast<const uint32_t*>(s1b);
    const uint32_t* w2 = reinterpret_cast<const uint32_t*>(s2b);
    uint32_t* d1 = reinterpret_cast<uint32_t*>(Fq + (size_t)n * 2 * K);
    uint32_t* d2 = reinterpret_cast<uint32_t*>(Fq + (size_t)n * 2 * K + K);
    for (int p = t; p < words; p += 256) {
        d1[p] = w1[p];
        d2[p] = w2[p];
    }
    if (t == 0) sF[n] = s1;
}

// ---------------------------------------------------------------------------
// Weight fold + per-output-row int8 quantize. Block = one output o.
//   Wq[o][2K] = [q1 | q2],  sW[o] = scale
// ---------------------------------------------------------------------------
__global__ __launch_bounds__(256)
void prep_weights_q8(const float* __restrict__ coef,
                     const float* __restrict__ sbase,
                     const float* __restrict__ ssp,
                     int8_t* __restrict__ Wq, float* __restrict__ sW,
                     int I, int O) {
    __shared__ float red[256];
    __shared__ __align__(16) int8_t s1b[1024 * NFEAT];
    __shared__ __align__(16) int8_t s2b[1024 * NFEAT];
    const int o = blockIdx.x;
    const int t = threadIdx.x;
    const int ipt = I >> 8;
    const int K = I * NFEAT;

    float w[4][NFEAT];
    float lmax = 1e-20f;
#pragma unroll
    for (int r = 0; r < 4; r++) {
        if (r < ipt) {
            int i = t + (r << 8);
            size_t io = (size_t)i * O + o;
            float sp = ssp[io];
            w[r][0] = sbase[io];
            const float* c = coef + io * 8;
#pragma unroll
            for (int g = 0; g < 8; g++) w[r][1 + g] = c[g] * sp;
#pragma unroll
            for (int fi = 0; fi < NFEAT; fi++) lmax = fmaxf(lmax, fabsf(w[r][fi]));
        }
    }
    red[t] = lmax;
    __syncthreads();
    for (int off = 128; off > 0; off >>= 1) {
        if (t < off) red[t] = fmaxf(red[t], red[t + off]);
        __syncthreads();
    }
    const float maxw = red[0];
    const float s1   = maxw * (1.0f / 127.0f);
    const float inv1 = 127.0f / maxw;
    const float inv2 = inv1 * 254.0f;

#pragma unroll
    for (int r = 0; r < 4; r++) {
        if (r < ipt) {
            int i = t + (r << 8);
#pragma unroll
            for (int fi = 0; fi < NFEAT; fi++)
                quant2(w[r][fi], s1, inv1, inv2,
                       &s1b[i * NFEAT + fi], &s2b[i * NFEAT + fi]);
        }
    }
    __syncthreads();

    const int words = (I * NFEAT) >> 2;
    const uint32_t* w1 = reinterpret_cast<const uint32_t*>(s1b);
    const uint32_t* w2 = reinterpret_cast<const uint32_t*>(s2b);
    uint32_t* d1 = reinterpret_cast<uint32_t*>(Wq + (size_t)o * 2 * K);
    uint32_t* d2 = reinterpret_cast<uint32_t*>(Wq + (size_t)o * 2 * K + K);
    for (int p = t; p < words; p += 256) {
        d1[p] = w1[p];
        d2[p] = w2[p];
    }
    if (t == 0) sW[o] = s1;
}

// ---------------------------------------------------------------------------
// int8 GEMM:  S_z[m][o] = sum_c A[term-chunk][m] . B[term-chunk][o]  (s32)
// CTA 128x128, 4 warps 64x64, chunk = 128 int8 (128B rows, same swizzle/
// cp.async/ldmatrix byte layout as the validated bf16 kernel).
// z = blockIdx.z: term = z%3 (0: q1.q1, 1: q1a.q2b, 2: q2a.q1b),
//                 ksplit slice = z/3.
// ---------------------------------------------------------------------------
#define A_BYTES      (128 * 128)
#define STAGE_BYTES  (2 * A_BYTES)
#define SMEM_GEMM    (3 * STAGE_BYTES)

__global__ __launch_bounds__(128, 2)
void kan_gemm_s8(const int8_t* __restrict__ A, const int8_t* __restrict__ B,
                 int* __restrict__ S,
                 int nK, int nchunks, int PKa, int PKb, int ldc, size_t csplit) {
    extern __shared__ __align__(1024) char smem_raw[];
    const uint32_t sb = smem_u32(smem_raw);

    const int tid  = threadIdx.x;
    const int lane = tid & 31;
    const int wid  = tid >> 5;
    const int m0w  = (wid & 1) * 64;
    const int n0w  = (wid >> 1) * 64;
    const int m0   = blockIdx.y * 128;
    const int o0   = blockIdx.x * 128;
    const int z    = blockIdx.z;
    const int term = z % 3;
    const int c0   = (z / 3) * nchunks;
    int* Sz        = S + (size_t)z * csplit;

    const int8_t* Abase = A + (size_t)m0 * PKa + (size_t)(((term == 2) ? nK : 0) + c0) * 128;
    const int8_t* Bbase = B + (size_t)o0 * PKb + (size_t)(((term == 1) ? nK : 0) + c0) * 128;

    const int r0   = tid >> 3;
    const int c16t = tid & 7;

    int acc[4][8][4];
#pragma unroll
    for (int mi = 0; mi < 4; mi++)
#pragma unroll
        for (int nj = 0; nj < 8; nj++)
#pragma unroll
            for (int e = 0; e < 4; e++) acc[mi][nj][e] = 0;

    auto load_chunk = [&](int c, int s) {
        const uint32_t aB = sb + s * STAGE_BYTES;
        const uint32_t bB = aB + A_BYTES;
        const int8_t* Ap = Abase + (size_t)c * 128 + c16t * 16;
        const int8_t* Bp = Bbase + (size_t)c * 128 + c16t * 16;
#pragma unroll
        for (int it = 0; it < 8; it++) {
            int row = r0 + it * 16;
            CP_ASYNC16(lds_addr(aB, row, c16t), Ap + (size_t)row * PKa);
        }
#pragma unroll
        for (int it = 0; it < 8; it++) {
            int row = r0 + it * 16;
            CP_ASYNC16(lds_addr(bB, row, c16t), Bp + (size_t)row * PKb);
        }
    };

    uint32_t fa[2][4][4], fb[2][4][4];
    auto load_frags = [&](uint32_t aB, uint32_t bB, int kk, int buf) {
#pragma unroll
        for (int mi = 0; mi < 4; mi++)
            ldsm_x4(fa[buf][mi], lds_addr(aB, m0w + mi * 16 + (lane & 15),
                                          kk * 2 + (lane >> 4)));
#pragma unroll
        for (int nj2 = 0; nj2 < 4; nj2++) {
            int rowB = n0w + nj2 * 16 + ((lane >> 4) << 3) + (lane & 7);
            int colB = kk * 2 + ((lane >> 3) & 1);
            ldsm_x4(fb[buf][nj2], lds_addr(bB, rowB, colB));
        }
    };

    load_chunk(0, 0); CP_COMMIT();
    load_chunk(1, 1); CP_COMMIT();

    for (int cc = 0; cc < nchunks; cc++) {
        CP_WAIT1();
        __syncthreads();
        if (cc + 2 < nchunks) load_chunk(cc + 2, (cc + 2) % 3);
        CP_COMMIT();

        const uint32_t aB = sb + (cc % 3) * STAGE_BYTES;
        const uint32_t bB = aB + A_BYTES;
        load_frags(aB, bB, 0, 0);
#pragma unroll
        for (int kk = 0; kk < 4; kk++) {
            const int cur = kk & 1;
            if (kk < 3) load_frags(aB, bB, kk + 1, cur ^ 1);
#pragma unroll
            for (int mi = 0; mi < 4; mi++)
#pragma unroll
                for (int nj = 0; nj < 8; nj++)
                    mma16832s8(acc[mi][nj], fa[cur][mi], &fb[cur][nj >> 1][(nj & 1) * 2]);
        }
    }

    const int g   = lane >> 2;
    const int cc0 = (lane & 3) * 2;
#pragma unroll
    for (int mi = 0; mi < 4; mi++) {
#pragma unroll
        for (int nj = 0; nj < 8; nj++) {
            int row = m0 + m0w + mi * 16 + g;
            int col = o0 + n0w + nj * 8 + cc0;
            int2 v0 = make_int2(acc[mi][nj][0], acc[mi][nj][1]);
            int2 v1 = make_int2(acc[mi][nj][2], acc[mi][nj][3]);
            *reinterpret_cast<int2*>(&Sz[(size_t)row * ldc + col]) = v0;
            *reinterpret_cast<int2*>(&Sz[(size_t)(row + 8) * ldc + col]) = v1;
        }
    }
}

// ---------------------------------------------------------------------------
// Combine slabs:  out[n][o] = sA[n]*sB[o]*( hi + cross/254 )
// term weight by z%3: z%3==0 -> hi, else cross. int4-vectorized.
// ---------------------------------------------------------------------------
__global__ void combine_out(const int* __restrict__ S,
                            const float* __restrict__ sA,
                            const float* __restrict__ sB,
                            float* __restrict__ out,
                            int O, int nz, size_t stride, int total4) {
    int i = blockIdx.x * blockDim.x + threadIdx.x;
    if (i >= total4) return;
    const int per4 = O >> 2;
    const int n  = i / per4;
    const int o4 = (i - n * per4) << 2;

    int hi[4] = {0, 0, 0, 0}, cr[4] = {0, 0, 0, 0};
    for (int z = 0; z < nz; z++) {
        int4 v = reinterpret_cast<const int4*>(S + z * stride)[i];
        if (z % 3 == 0) { hi[0] += v.x; hi[1] += v.y; hi[2] += v.z; hi[3] += v.w; }
        else            { cr[0] += v.x; cr[1] += v.y; cr[2] += v.z; cr[3] += v.w; }
    }
    const float sa = sA[n];
    float4 sb = *reinterpret_cast<const float4*>(sB + o4);
    float4 r;
    r.x = sa * sb.x * ((float)hi[0] + (float)cr[0] * INV254);
    r.y = sa * sb.y * ((float)hi[1] + (float)cr[1] * INV254);
    r.z = sa * sb.z * ((float)hi[2] + (float)cr[2] * INV254);
    r.w = sa * sb.w * ((float)hi[3] + (float)cr[3] * INV254);
    *reinterpret_cast<float4*>(out + (size_t)n * O + o4) = r;
}

// ---------------------------------------------------------------------------
// Launch
// ---------------------------------------------------------------------------
extern "C" void kernel_launch(void* const* d_in, const int* in_sizes, int n_in,
                              void* d_out, int out_size) {
    const float* x   = (const float*)d_in[0];
    const float* c1  = (const float*)d_in[1];
    const float* sb1 = (const float*)d_in[2];
    const float* sp1 = (const float*)d_in[3];
    const float* c2  = (const float*)d_in[4];
    const float* sb2 = (const float*)d_in[5];
    const float* sp2 = (const float*)d_in[6];
    float* out = (float*)d_out;

    const int D = D_MODEL, H = HIDDEN;
    const int N = in_sizes[0] / D;   // 4096

    void *pF, *pW1, *pW2, *pS, *pH, *psF, *psW1, *psW2;
    cudaGetSymbolAddress(&pF,   g_F);
    cudaGetSymbolAddress(&pW1,  g_W1);
    cudaGetSymbolAddress(&pW2,  g_W2);
    cudaGetSymbolAddress(&pS,   g_S);
    cudaGetSymbolAddress(&pH,   g_h);
    cudaGetSymbolAddress(&psF,  g_sF);
    cudaGetSymbolAddress(&psW1, g_sW1);
    cudaGetSymbolAddress(&psW2, g_sW2);
    int8_t* Fq  = (int8_t*)pF;
    int8_t* W1q = (int8_t*)pW1;
    int8_t* W2q = (int8_t*)pW2;
    int*    S   = (int*)pS;
    float*  hb  = (float*)pH;
    float*  sF  = (float*)psF;
    float*  sW1 = (float*)psW1;
    float*  sW2 = (float*)psW2;

    static bool attr_set = false;
    if (!attr_set) {
        cudaFuncSetAttribute(kan_gemm_s8,
                             cudaFuncAttributeMaxDynamicSharedMemorySize, SMEM_GEMM);
        attr_set = true;
    }

    // Fold + quantize weights
    prep_weights_q8<<<H, 256>>>(c1, sb1, sp1, W1q, sW1, D, H);
    prep_weights_q8<<<D, 256>>>(c2, sb2, sp2, W2q, sW2, H, D);

    // Layer 1: nK = K1/128 = 36 chunks/term, 3 terms, no k-split
    build_features_q8<<<N, 256>>>(x, Fq, sF, D);
    kan_gemm_s8<<<dim3(H / 128, N / 128, 3), 128, SMEM_GEMM>>>(
        Fq, W1q, S, K1 / 128, K1 / 128, 2 * K1, 2 * K1, H, (size_t)N * H);
    combine_out<<<(N * H / 4 + 255) / 256, 256>>>(
        S, sF, sW1, hb, H, 3, (size_t)N * H, N * H / 4);

    // Layer 2: nK = K2/128 = 72, k-split 2 -> 6 z-slabs of 36 chunks
    build_features_q8<<<N, 256>>>(hb, Fq, sF, H);
    kan_gemm_s8<<<dim3(D / 128, N / 128, 6), 128, SMEM_GEMM>>>(
        Fq, W2q, S, K2 / 128, K2 / 256, 2 * K2, 2 * K2, D, (size_t)N * D);
    combine_out<<<(N * D / 4 + 255) / 256, 256>>>(
        S, sF, sW2, out, D, 6, (size_t)N * D, N * D / 4);
}

// round 9
// speedup vs baseline: 2.3559x; 2.3559x over previous
#include <cuda_runtime.h>
#include <cuda_bf16.h>
#include <math.h>
#include <stdint.h>

// ---------------------------------------------------------------------------
// KAN feedforward, bf16 3-term split (validated R5-R7, rel_err ~6e-5):
//   Logical A' = [Fhi | Fhi | Flo], B' = [Whi | Wlo | Whi]  (Keff = 3K)
//   Stored deduped: F = [Fhi | Flo], W = [Whi | Wlo]  (2K), chunk-remapped.
// R9: (a) GEMM2 split-K8 for per-SM chunk balance (378 vs 432 on critical SM)
//     (b) layer-2 feature build fused into GEMM1 epilogue (h never stored)
//     (c) 8-slab deterministic reduction.
// ---------------------------------------------------------------------------

#define D_MODEL 512
#define HIDDEN  1024
#define NFEAT   9
#define NTOK    4096
#define K1      (D_MODEL * NFEAT)   // 4608
#define K2      (HIDDEN  * NFEAT)   // 9216

__device__ __nv_bfloat16 g_F1 [(size_t)NTOK * 2 * K1];     // 75.5 MB L1 features
__device__ __nv_bfloat16 g_F2 [(size_t)NTOK * 2 * K2];     // 151 MB  L2 features
__device__ __nv_bfloat16 g_W1 [(size_t)HIDDEN * 2 * K1];   // 18.9 MB
__device__ __nv_bfloat16 g_W2 [(size_t)D_MODEL * 2 * K2];  // 18.9 MB
__device__ int           g_Sd [(size_t)8 * NTOK * D_MODEL];// 67 MB (fp32 slabs)

// ---------------------------------------------------------------------------
// Helpers
// ---------------------------------------------------------------------------
__device__ __forceinline__ uint32_t smem_u32(const void* p) {
    uint32_t a;
    asm("{ .reg .u64 t; cvta.to.shared.u64 t, %1; cvt.u32.u64 %0, t; }"
        : "=r"(a) : "l"(p));
    return a;
}

__device__ __forceinline__ uint32_t lds_addr(uint32_t base, int row, int col16) {
    return base + row * 128 + ((col16 ^ (row & 7)) << 4);
}

#define CP_ASYNC16(sm, gm)                                                    \
    asm volatile("cp.async.cg.shared.global [%0], [%1], 16;"                  \
                 :: "r"(sm), "l"(gm) : "memory")
#define CP_COMMIT()  asm volatile("cp.async.commit_group;" ::: "memory")
#define CP_WAIT1()   asm volatile("cp.async.wait_group 1;" ::: "memory")
#define CP_WAIT0()   asm volatile("cp.async.wait_group 0;" ::: "memory")

__device__ __forceinline__ void ldsm_x4(uint32_t r[4], uint32_t addr) {
    asm volatile("ldmatrix.sync.aligned.m8n8.x4.shared.b16 {%0,%1,%2,%3}, [%4];"
                 : "=r"(r[0]), "=r"(r[1]), "=r"(r[2]), "=r"(r[3]) : "r"(addr));
}

__device__ __forceinline__ void mma16816(float c[4], const uint32_t a[4],
                                         const uint32_t b[2]) {
    asm volatile(
        "mma.sync.aligned.m16n8k16.row.col.f32.bf16.bf16.f32 "
        "{%0,%1,%2,%3}, {%4,%5,%6,%7}, {%8,%9}, {%0,%1,%2,%3};"
        : "+f"(c[0]), "+f"(c[1]), "+f"(c[2]), "+f"(c[3])
        : "r"(a[0]), "r"(a[1]), "r"(a[2]), "r"(a[3]), "r"(b[0]), "r"(b[1]));
}

// ---------------------------------------------------------------------------
// Spline features (validated R3-R7)
// ---------------------------------------------------------------------------
__device__ __forceinline__ float knotf(int k) {
    return __fadd_rn(__fmul_rn((float)(k - 3), 0.4f), -1.0f);
}

__device__ __forceinline__ void kan_features(float x, float f[NFEAT]) {
    float sig = 1.0f / (1.0f + expf(-x));
    f[0] = x * sig;
#pragma unroll
    for (int g = 0; g < 8; g++) f[1 + g] = 0.0f;

    float u = (x - knotf(0)) * 2.5f;
    if (u > 16.0f) u = 16.0f;
    if (u < -16.0f) u = -16.0f;
    int j = (int)floorf(u);
    if (j < -1) j = -1;
    if (j > 11) j = 11;
    if (x < knotf(j))            j -= 1;
    else if (x >= knotf(j + 1))  j += 1;
    if (j < 0 || j > 10) return;

    float s  = (x - knotf(j)) * 2.5f;
    float s2 = s * s, s3 = s2 * s;
    float om = 1.0f - s;
    float w0 = om * om * om * (1.0f / 6.0f);
    float w1 = (3.0f * s3 - 6.0f * s2 + 4.0f) * (1.0f / 6.0f);
    float w2 = (-3.0f * s3 + 3.0f * s2 + 3.0f * s + 1.0f) * (1.0f / 6.0f);
    float w3 = s3 * (1.0f / 6.0f);
    float w[4] = {w0, w1, w2, w3};
    int g0 = j - 3;
#pragma unroll
    for (int r = 0; r < 4; r++) {
        int g = g0 + r;
        if (g >= 0 && g < 8) f[1 + g] = w[r];
    }
}

// ---------------------------------------------------------------------------
// Coalesced feature expand + quantize (layer 1):  Fq[n][2K] = [Fhi | Flo]
// ---------------------------------------------------------------------------
__global__ __launch_bounds__(256)
void build_features_q(const float* __restrict__ X,
                      __nv_bfloat16* __restrict__ Fq, int I) {
    __shared__ __align__(16) __nv_bfloat16 sh[256 * NFEAT];
    __shared__ __align__(16) __nv_bfloat16 sl[256 * NFEAT];
    const int n  = blockIdx.x;
    const int i0 = blockIdx.y << 8;
    const int t  = threadIdx.x;
    const int K  = I * NFEAT;

    float x = X[(size_t)n * I + i0 + t];
    float f[NFEAT];
    kan_features(x, f);
#pragma unroll
    for (int fi = 0; fi < NFEAT; fi++) {
        __nv_bfloat16 h = __float2bfloat16(f[fi]);
        sh[t * NFEAT + fi] = h;
        sl[t * NFEAT + fi] = __float2bfloat16(f[fi] - __bfloat162float(h));
    }
    __syncthreads();

    const uint32_t* s32h = reinterpret_cast<const uint32_t*>(sh);
    const uint32_t* s32l = reinterpret_cast<const uint32_t*>(sl);
    size_t base = (size_t)n * 2 * K + (size_t)i0 * NFEAT;
    uint32_t* dh = reinterpret_cast<uint32_t*>(Fq + base);
    uint32_t* dl = reinterpret_cast<uint32_t*>(Fq + base + K);
    for (int p = t; p < 1152; p += 256) {
        dh[p] = s32h[p];
        dl[p] = s32l[p];
    }
}

// ---------------------------------------------------------------------------
// Coalesced weight fold + quantize:  Wq[o][2K] = [Whi | Wlo]
// ---------------------------------------------------------------------------
__global__ __launch_bounds__(256)
void prep_weights_q(const float* __restrict__ coef,
                    const float* __restrict__ sbase,
                    const float* __restrict__ ssp,
                    __nv_bfloat16* __restrict__ Wq, int I, int O) {
    __shared__ __align__(16) __nv_bfloat16 sh[256 * NFEAT];
    __shared__ __align__(16) __nv_bfloat16 sl[256 * NFEAT];
    const int o  = blockIdx.x;
    const int i0 = blockIdx.y << 8;
    const int t  = threadIdx.x;
    const int K  = I * NFEAT;
    const int i  = i0 + t;

    size_t io = (size_t)i * O + o;
    float sp = ssp[io];
    float w[NFEAT];
    w[0] = sbase[io];
    const float* c = coef + io * 8;
#pragma unroll
    for (int g = 0; g < 8; g++) w[1 + g] = c[g] * sp;

#pragma unroll
    for (int fi = 0; fi < NFEAT; fi++) {
        __nv_bfloat16 h = __float2bfloat16(w[fi]);
        sh[t * NFEAT + fi] = h;
        sl[t * NFEAT + fi] = __float2bfloat16(w[fi] - __bfloat162float(h));
    }
    __syncthreads();

    const uint32_t* s32h = reinterpret_cast<const uint32_t*>(sh);
    const uint32_t* s32l = reinterpret_cast<const uint32_t*>(sl);
    size_t base = (size_t)o * 2 * K + (size_t)i0 * NFEAT;
    uint32_t* dh = reinterpret_cast<uint32_t*>(Wq + base);
    uint32_t* dl = reinterpret_cast<uint32_t*>(Wq + base + K);
    for (int p = t; p < 1152; p += 256) {
        dh[p] = s32h[p];
        dl[p] = s32l[p];
    }
}

// ---------------------------------------------------------------------------
// GEMM (R7 mainloop, unchanged):  acc[m][o] = sum_c A'[m][.] * B'[o][.]
// FUSE=true : epilogue computes L2 features from acc (h never stored) -> Fout
// FUSE=false: epilogue stores fp32 slab C (split-K via blockIdx.z)
// ---------------------------------------------------------------------------
#define GEMM_BK      64
#define A_BYTES      (128 * 128)
#define STAGE_BYTES  (2 * A_BYTES)
#define SMEM_GEMM    (3 * STAGE_BYTES)

template <bool FUSE>
__global__ __launch_bounds__(128, 2)
void kan_gemm_mma(const __nv_bfloat16* __restrict__ A,
                  const __nv_bfloat16* __restrict__ B,
                  float* __restrict__ C,
                  __nv_bfloat16* __restrict__ Fout,
                  int nK, int nchunks, int PK, int ldc, size_t csplit) {
    extern __shared__ __align__(1024) char smem_raw[];
    const uint32_t sb = smem_u32(smem_raw);

    const int tid  = threadIdx.x;
    const int lane = tid & 31;
    const int wid  = tid >> 5;
    const int m0w  = (wid & 1) * 64;
    const int n0w  = (wid >> 1) * 64;
    const int m0   = blockIdx.y * 128;
    const int o0   = blockIdx.x * 128;
    const int z0   = blockIdx.z * nchunks;

    const __nv_bfloat16* Arow = A + (size_t)m0 * PK;
    const __nv_bfloat16* Brow = B + (size_t)o0 * PK;

    const int r0   = tid >> 3;
    const int c16t = tid & 7;

    float acc[4][8][4];
#pragma unroll
    for (int mi = 0; mi < 4; mi++)
#pragma unroll
        for (int nj = 0; nj < 8; nj++)
#pragma unroll
            for (int e = 0; e < 4; e++) acc[mi][nj][e] = 0.0f;

    auto a_chunk = [&](int c) -> const __nv_bfloat16* {
        int p = (c < nK) ? c : c - nK;
        return Arow + (size_t)p * GEMM_BK;
    };
    auto b_chunk = [&](int c) -> const __nv_bfloat16* {
        int p = (c < 2 * nK) ? c : c - 2 * nK;
        return Brow + (size_t)p * GEMM_BK;
    };

    auto load_chunk = [&](int logical_c, int s) {
        const uint32_t aB = sb + s * STAGE_BYTES;
        const uint32_t bB = aB + A_BYTES;
        const __nv_bfloat16* Ap = a_chunk(logical_c) + c16t * 8;
        const __nv_bfloat16* Bp = b_chunk(logical_c) + c16t * 8;
#pragma unroll
        for (int it = 0; it < 8; it++) {
            int row = r0 + it * 16;
            CP_ASYNC16(lds_addr(aB, row, c16t), Ap + (size_t)row * PK);
        }
#pragma unroll
        for (int it = 0; it < 8; it++) {
            int row = r0 + it * 16;
            CP_ASYNC16(lds_addr(bB, row, c16t), Bp + (size_t)row * PK);
        }
    };

    uint32_t fa[2][4][4], fb[2][4][4];
    auto load_frags = [&](uint32_t aB, uint32_t bB, int kk, int buf) {
#pragma unroll
        for (int mi = 0; mi < 4; mi++)
            ldsm_x4(fa[buf][mi], lds_addr(aB, m0w + mi * 16 + (lane & 15),
                                          kk * 2 + (lane >> 4)));
#pragma unroll
        for (int nj2 = 0; nj2 < 4; nj2++) {
            int rowB = n0w + nj2 * 16 + ((lane >> 4) << 3) + (lane & 7);
            int colB = kk * 2 + ((lane >> 3) & 1);
            ldsm_x4(fb[buf][nj2], lds_addr(bB, rowB, colB));
        }
    };

    load_chunk(z0 + 0, 0); CP_COMMIT();
    load_chunk(z0 + 1, 1); CP_COMMIT();

    for (int cc = 0; cc < nchunks; cc++) {
        CP_WAIT1();
        __syncthreads();
        if (cc + 2 < nchunks) load_chunk(z0 + cc + 2, (cc + 2) % 3);
        CP_COMMIT();

        const uint32_t aB = sb + (cc % 3) * STAGE_BYTES;
        const uint32_t bB = aB + A_BYTES;
        load_frags(aB, bB, 0, 0);
#pragma unroll
        for (int kk = 0; kk < 4; kk++) {
            const int cur = kk & 1;
            if (kk < 3) load_frags(aB, bB, kk + 1, cur ^ 1);
#pragma unroll
            for (int mi = 0; mi < 4; mi++)
#pragma unroll
                for (int nj = 0; nj < 8; nj++)
                    mma16816(acc[mi][nj], fa[cur][mi], &fb[cur][nj >> 1][(nj & 1) * 2]);
        }
    }

    const int g   = lane >> 2;
    const int cc0 = (lane & 3) * 2;

    if (!FUSE) {
        float* Cz = C + (size_t)blockIdx.z * csplit;
#pragma unroll
        for (int mi = 0; mi < 4; mi++) {
#pragma unroll
            for (int nj = 0; nj < 8; nj++) {
                int row = m0 + m0w + mi * 16 + g;
                int col = o0 + n0w + nj * 8 + cc0;
                float2 v0 = make_float2(acc[mi][nj][0], acc[mi][nj][1]);
                float2 v1 = make_float2(acc[mi][nj][2], acc[mi][nj][3]);
                *reinterpret_cast<float2*>(&Cz[(size_t)row * ldc + col]) = v0;
                *reinterpret_cast<float2*>(&Cz[(size_t)(row + 8) * ldc + col]) = v1;
            }
        }
    } else {
        // Fused layer-2 feature build: acc holds h[128 tok x 128 dims].
        // 8 groups (nj = gg): 16 cols/group (two 8-col bands), staged in smem.
        CP_WAIT0();
        __syncthreads();
        __nv_bfloat16* sHi = reinterpret_cast<__nv_bfloat16*>(smem_raw);
        __nv_bfloat16* sLo = sHi + 128 * 144;        // 36.9 KB each
#pragma unroll
        for (int gg = 0; gg < 8; gg++) {
#pragma unroll
            for (int mi = 0; mi < 4; mi++) {
#pragma unroll
                for (int e = 0; e < 4; e++) {
                    int row  = m0w + mi * 16 + g + (e >> 1) * 8;
                    int colL = n0w + gg * 8 + cc0 + (e & 1);
                    float hv = acc[mi][gg][e];
                    float f[NFEAT];
                    kan_features(hv, f);
                    int dimg = ((colL >> 6) << 3) + (colL & 7);   // 0..15
                    __nv_bfloat16* ph = &sHi[row * 144 + dimg * 9];
                    __nv_bfloat16* pl = &sLo[row * 144 + dimg * 9];
#pragma unroll
                    for (int fi = 0; fi < NFEAT; fi++) {
                        __nv_bfloat16 hb = __float2bfloat16(f[fi]);
                        ph[fi] = hb;
                        pl[fi] = __float2bfloat16(f[fi] - __bfloat162float(hb));
                    }
                }
            }
            __syncthreads();
            // copy out: per row, two 8-dim bands of 72 bf16 (36 words) each
            const uint32_t* wHi = reinterpret_cast<const uint32_t*>(sHi);
            const uint32_t* wLo = reinterpret_cast<const uint32_t*>(sLo);
            for (int w = tid; w < 128 * 72; w += 128) {
                int row = w / 72;
                int wi  = w - row * 72;
                int bd  = wi / 36;
                int wo  = wi - bd * 36;
                size_t tok  = m0 + row;
                size_t elem = tok * (size_t)(2 * K2)
                            + (size_t)(o0 + bd * 64 + gg * 8) * NFEAT + wo * 2;
                *reinterpret_cast<uint32_t*>(Fout + elem)      = wHi[w];
                *reinterpret_cast<uint32_t*>(Fout + elem + K2) = wLo[w];
            }
            __syncthreads();
        }
    }
}

// ---------------------------------------------------------------------------
// 8-slab deterministic reduction: out = sum_z S[z]
// ---------------------------------------------------------------------------
__global__ void add_splits8(const float* __restrict__ s, float* __restrict__ out,
                            size_t stride, int n4) {
    int i = blockIdx.x * blockDim.x + threadIdx.x;
    if (i >= n4) return;
    float4 a = reinterpret_cast<const float4*>(s)[i];
#pragma unroll
    for (int z = 1; z < 8; z++) {
        float4 b = reinterpret_cast<const float4*>(s + z * stride)[i];
        a.x += b.x; a.y += b.y; a.z += b.z; a.w += b.w;
    }
    *reinterpret_cast<float4*>(out + (size_t)i * 4) = a;
}

// ---------------------------------------------------------------------------
// Launch
// ---------------------------------------------------------------------------
extern "C" void kernel_launch(void* const* d_in, const int* in_sizes, int n_in,
                              void* d_out, int out_size) {
    const float* x   = (const float*)d_in[0];
    const float* c1  = (const float*)d_in[1];
    const float* sb1 = (const float*)d_in[2];
    const float* sp1 = (const float*)d_in[3];
    const float* c2  = (const float*)d_in[4];
    const float* sb2 = (const float*)d_in[5];
    const float* sp2 = (const float*)d_in[6];
    float* out = (float*)d_out;

    const int D = D_MODEL, H = HIDDEN;
    const int N = in_sizes[0] / D;   // 4096

    void *pF1, *pF2, *pW1, *pW2, *pS;
    cudaGetSymbolAddress(&pF1, g_F1);
    cudaGetSymbolAddress(&pF2, g_F2);
    cudaGetSymbolAddress(&pW1, g_W1);
    cudaGetSymbolAddress(&pW2, g_W2);
    cudaGetSymbolAddress(&pS,  g_Sd);
    __nv_bfloat16* F1  = (__nv_bfloat16*)pF1;
    __nv_bfloat16* F2  = (__nv_bfloat16*)pF2;
    __nv_bfloat16* W1q = (__nv_bfloat16*)pW1;
    __nv_bfloat16* W2q = (__nv_bfloat16*)pW2;
    float* S = (float*)pS;

    static bool attr_set = false;
    if (!attr_set) {
        cudaFuncSetAttribute(kan_gemm_mma<true>,
                             cudaFuncAttributeMaxDynamicSharedMemorySize, SMEM_GEMM);
        cudaFuncSetAttribute(kan_gemm_mma<false>,
                             cudaFuncAttributeMaxDynamicSharedMemorySize, SMEM_GEMM);
        attr_set = true;
    }

    // Fold + quantize weights
    prep_weights_q<<<dim3(H, D / 256), 256>>>(c1, sb1, sp1, W1q, D, H);
    prep_weights_q<<<dim3(D, H / 256), 256>>>(c2, sb2, sp2, W2q, H, D);

    // Layer 1 features
    build_features_q<<<dim3(N, D / 256), 256>>>(x, F1, D);

    // GEMM1 (fused epilogue -> layer-2 features, h never materialized)
    kan_gemm_mma<true><<<dim3(H / 128, N / 128, 1), 128, SMEM_GEMM>>>(
        F1, W1q, nullptr, F2, K1 / 64, 3 * (K1 / 64), 2 * K1, H, 0);

    // GEMM2: split-K 8 for per-SM balance (1024 CTAs x 54 chunks)
    kan_gemm_mma<false><<<dim3(D / 128, N / 128, 8), 128, SMEM_GEMM>>>(
        F2, W2q, S, nullptr, K2 / 64, (3 * (K2 / 64)) / 8, 2 * K2, D,
        (size_t)N * D);

    add_splits8<<<(N * D / 4 + 255) / 256, 256>>>(S, out, (size_t)N * D, N * D / 4);
}

// round 10
// speedup vs baseline: 2.9828x; 1.2661x over previous
#include <cuda_runtime.h>
#include <cuda_bf16.h>
#include <math.h>
#include <stdint.h>

// ---------------------------------------------------------------------------
// KAN feedforward, bf16 3-term split (validated R5-R7, rel_err ~6e-5):
//   Logical A' = [Fhi | Fhi | Flo], B' = [Whi | Wlo | Whi]  (Keff = 3K)
//   Stored deduped: F = [Fhi | Flo], W = [Whi | Wlo]  (2K), chunk-remapped.
// R10: R7 pipeline + split-K on BOTH GEMMs for per-SM chunk balance
//      (busiest SM 378 vs 432 chunks), fixed-order slab reduction.
// ---------------------------------------------------------------------------

#define D_MODEL 512
#define HIDDEN  1024
#define NFEAT   9
#define NTOK    4096
#define K1      (D_MODEL * NFEAT)   // 4608
#define K2      (HIDDEN  * NFEAT)   // 9216

__device__ __nv_bfloat16 g_F  [(size_t)NTOK * 2 * K2];     // 151 MB (both layers)
__device__ __nv_bfloat16 g_W1 [(size_t)HIDDEN * 2 * K1];   // 18.9 MB
__device__ __nv_bfloat16 g_W2 [(size_t)D_MODEL * 2 * K2];  // 18.9 MB
__device__ float g_Sd [(size_t)8 * NTOK * D_MODEL];        // 67 MB slabs (4xNH == 8xND)
__device__ float g_h  [(size_t)NTOK * HIDDEN];             // 16 MB

// ---------------------------------------------------------------------------
// Helpers
// ---------------------------------------------------------------------------
__device__ __forceinline__ uint32_t smem_u32(const void* p) {
    uint32_t a;
    asm("{ .reg .u64 t; cvta.to.shared.u64 t, %1; cvt.u32.u64 %0, t; }"
        : "=r"(a) : "l"(p));
    return a;
}

__device__ __forceinline__ uint32_t lds_addr(uint32_t base, int row, int col16) {
    return base + row * 128 + ((col16 ^ (row & 7)) << 4);
}

#define CP_ASYNC16(sm, gm)                                                    \
    asm volatile("cp.async.cg.shared.global [%0], [%1], 16;"                  \
                 :: "r"(sm), "l"(gm) : "memory")
#define CP_COMMIT()  asm volatile("cp.async.commit_group;" ::: "memory")
#define CP_WAIT1()   asm volatile("cp.async.wait_group 1;" ::: "memory")

__device__ __forceinline__ void ldsm_x4(uint32_t r[4], uint32_t addr) {
    asm volatile("ldmatrix.sync.aligned.m8n8.x4.shared.b16 {%0,%1,%2,%3}, [%4];"
                 : "=r"(r[0]), "=r"(r[1]), "=r"(r[2]), "=r"(r[3]) : "r"(addr));
}

__device__ __forceinline__ void mma16816(float c[4], const uint32_t a[4],
                                         const uint32_t b[2]) {
    asm volatile(
        "mma.sync.aligned.m16n8k16.row.col.f32.bf16.bf16.f32 "
        "{%0,%1,%2,%3}, {%4,%5,%6,%7}, {%8,%9}, {%0,%1,%2,%3};"
        : "+f"(c[0]), "+f"(c[1]), "+f"(c[2]), "+f"(c[3])
        : "r"(a[0]), "r"(a[1]), "r"(a[2]), "r"(a[3]), "r"(b[0]), "r"(b[1]));
}

// ---------------------------------------------------------------------------
// Spline features (validated R3-R7)
// ---------------------------------------------------------------------------
__device__ __forceinline__ float knotf(int k) {
    return __fadd_rn(__fmul_rn((float)(k - 3), 0.4f), -1.0f);
}

__device__ __forceinline__ void kan_features(float x, float f[NFEAT]) {
    float sig = 1.0f / (1.0f + expf(-x));
    f[0] = x * sig;
#pragma unroll
    for (int g = 0; g < 8; g++) f[1 + g] = 0.0f;

    float u = (x - knotf(0)) * 2.5f;
    if (u > 16.0f) u = 16.0f;
    if (u < -16.0f) u = -16.0f;
    int j = (int)floorf(u);
    if (j < -1) j = -1;
    if (j > 11) j = 11;
    if (x < knotf(j))            j -= 1;
    else if (x >= knotf(j + 1))  j += 1;
    if (j < 0 || j > 10) return;

    float s  = (x - knotf(j)) * 2.5f;
    float s2 = s * s, s3 = s2 * s;
    float om = 1.0f - s;
    float w0 = om * om * om * (1.0f / 6.0f);
    float w1 = (3.0f * s3 - 6.0f * s2 + 4.0f) * (1.0f / 6.0f);
    float w2 = (-3.0f * s3 + 3.0f * s2 + 3.0f * s + 1.0f) * (1.0f / 6.0f);
    float w3 = s3 * (1.0f / 6.0f);
    float w[4] = {w0, w1, w2, w3};
    int g0 = j - 3;
#pragma unroll
    for (int r = 0; r < 4; r++) {
        int g = g0 + r;
        if (g >= 0 && g < 8) f[1 + g] = w[r];
    }
}

// ---------------------------------------------------------------------------
// Coalesced feature expand + quantize:  Fq[n][2K] = [Fhi | Flo]
// ---------------------------------------------------------------------------
__global__ __launch_bounds__(256)
void build_features_q(const float* __restrict__ X,
                      __nv_bfloat16* __restrict__ Fq, int I) {
    __shared__ __align__(16) __nv_bfloat16 sh[256 * NFEAT];
    __shared__ __align__(16) __nv_bfloat16 sl[256 * NFEAT];
    const int n  = blockIdx.x;
    const int i0 = blockIdx.y << 8;
    const int t  = threadIdx.x;
    const int K  = I * NFEAT;

    float x = X[(size_t)n * I + i0 + t];
    float f[NFEAT];
    kan_features(x, f);
#pragma unroll
    for (int fi = 0; fi < NFEAT; fi++) {
        __nv_bfloat16 h = __float2bfloat16(f[fi]);
        sh[t * NFEAT + fi] = h;
        sl[t * NFEAT + fi] = __float2bfloat16(f[fi] - __bfloat162float(h));
    }
    __syncthreads();

    const uint32_t* s32h = reinterpret_cast<const uint32_t*>(sh);
    const uint32_t* s32l = reinterpret_cast<const uint32_t*>(sl);
    size_t base = (size_t)n * 2 * K + (size_t)i0 * NFEAT;
    uint32_t* dh = reinterpret_cast<uint32_t*>(Fq + base);
    uint32_t* dl = reinterpret_cast<uint32_t*>(Fq + base + K);
    for (int p = t; p < 1152; p += 256) {
        dh[p] = s32h[p];
        dl[p] = s32l[p];
    }
}

// ---------------------------------------------------------------------------
// Coalesced weight fold + quantize:  Wq[o][2K] = [Whi | Wlo]
// ---------------------------------------------------------------------------
__global__ __launch_bounds__(256)
void prep_weights_q(const float* __restrict__ coef,
                    const float* __restrict__ sbase,
                    const float* __restrict__ ssp,
                    __nv_bfloat16* __restrict__ Wq, int I, int O) {
    __shared__ __align__(16) __nv_bfloat16 sh[256 * NFEAT];
    __shared__ __align__(16) __nv_bfloat16 sl[256 * NFEAT];
    const int o  = blockIdx.x;
    const int i0 = blockIdx.y << 8;
    const int t  = threadIdx.x;
    const int K  = I * NFEAT;
    const int i  = i0 + t;

    size_t io = (size_t)i * O + o;
    float sp = ssp[io];
    float w[NFEAT];
    w[0] = sbase[io];
    const float* c = coef + io * 8;
#pragma unroll
    for (int g = 0; g < 8; g++) w[1 + g] = c[g] * sp;

#pragma unroll
    for (int fi = 0; fi < NFEAT; fi++) {
        __nv_bfloat16 h = __float2bfloat16(w[fi]);
        sh[t * NFEAT + fi] = h;
        sl[t * NFEAT + fi] = __float2bfloat16(w[fi] - __bfloat162float(h));
    }
    __syncthreads();

    const uint32_t* s32h = reinterpret_cast<const uint32_t*>(sh);
    const uint32_t* s32l = reinterpret_cast<const uint32_t*>(sl);
    size_t base = (size_t)o * 2 * K + (size_t)i0 * NFEAT;
    uint32_t* dh = reinterpret_cast<uint32_t*>(Wq + base);
    uint32_t* dl = reinterpret_cast<uint32_t*>(Wq + base + K);
    for (int p = t; p < 1152; p += 256) {
        dh[p] = s32h[p];
        dl[p] = s32l[p];
    }
}

// ---------------------------------------------------------------------------
// GEMM (R7 mainloop, unchanged; split-K slab via blockIdx.z):
//   S_z[m][o] = sum over this z's logical chunks of A'[m][.] * B'[o][.]
// ---------------------------------------------------------------------------
#define GEMM_BK      64
#define A_BYTES      (128 * 128)
#define STAGE_BYTES  (2 * A_BYTES)
#define SMEM_GEMM    (3 * STAGE_BYTES)

__global__ __launch_bounds__(128, 2)
void kan_gemm_mma(const __nv_bfloat16* __restrict__ A,
                  const __nv_bfloat16* __restrict__ B,
                  float* __restrict__ C,
                  int nK, int nchunks, int PK, int ldc, size_t csplit) {
    extern __shared__ __align__(1024) char smem_raw[];
    const uint32_t sb = smem_u32(smem_raw);

    const int tid  = threadIdx.x;
    const int lane = tid & 31;
    const int wid  = tid >> 5;
    const int m0w  = (wid & 1) * 64;
    const int n0w  = (wid >> 1) * 64;
    const int m0   = blockIdx.y * 128;
    const int o0   = blockIdx.x * 128;
    const int z0   = blockIdx.z * nchunks;
    float* Cz      = C + (size_t)blockIdx.z * csplit;

    const __nv_bfloat16* Arow = A + (size_t)m0 * PK;
    const __nv_bfloat16* Brow = B + (size_t)o0 * PK;

    const int r0   = tid >> 3;
    const int c16t = tid & 7;

    float acc[4][8][4];
#pragma unroll
    for (int mi = 0; mi < 4; mi++)
#pragma unroll
        for (int nj = 0; nj < 8; nj++)
#pragma unroll
            for (int e = 0; e < 4; e++) acc[mi][nj][e] = 0.0f;

    auto a_chunk = [&](int c) -> const __nv_bfloat16* {
        int p = (c < nK) ? c : c - nK;
        return Arow + (size_t)p * GEMM_BK;
    };
    auto b_chunk = [&](int c) -> const __nv_bfloat16* {
        int p = (c < 2 * nK) ? c : c - 2 * nK;
        return Brow + (size_t)p * GEMM_BK;
    };

    auto load_chunk = [&](int logical_c, int s) {
        const uint32_t aB = sb + s * STAGE_BYTES;
        const uint32_t bB = aB + A_BYTES;
        const __nv_bfloat16* Ap = a_chunk(logical_c) + c16t * 8;
        const __nv_bfloat16* Bp = b_chunk(logical_c) + c16t * 8;
#pragma unroll
        for (int it = 0; it < 8; it++) {
            int row = r0 + it * 16;
            CP_ASYNC16(lds_addr(aB, row, c16t), Ap + (size_t)row * PK);
        }
#pragma unroll
        for (int it = 0; it < 8; it++) {
            int row = r0 + it * 16;
            CP_ASYNC16(lds_addr(bB, row, c16t), Bp + (size_t)row * PK);
        }
    };

    uint32_t fa[2][4][4], fb[2][4][4];
    auto load_frags = [&](uint32_t aB, uint32_t bB, int kk, int buf) {
#pragma unroll
        for (int mi = 0; mi < 4; mi++)
            ldsm_x4(fa[buf][mi], lds_addr(aB, m0w + mi * 16 + (lane & 15),
                                          kk * 2 + (lane >> 4)));
#pragma unroll
        for (int nj2 = 0; nj2 < 4; nj2++) {
            int rowB = n0w + nj2 * 16 + ((lane >> 4) << 3) + (lane & 7);
            int colB = kk * 2 + ((lane >> 3) & 1);
            ldsm_x4(fb[buf][nj2], lds_addr(bB, rowB, colB));
        }
    };

    load_chunk(z0 + 0, 0); CP_COMMIT();
    load_chunk(z0 + 1, 1); CP_COMMIT();

    for (int cc = 0; cc < nchunks; cc++) {
        CP_WAIT1();
        __syncthreads();
        if (cc + 2 < nchunks) load_chunk(z0 + cc + 2, (cc + 2) % 3);
        CP_COMMIT();

        const uint32_t aB = sb + (cc % 3) * STAGE_BYTES;
        const uint32_t bB = aB + A_BYTES;
        load_frags(aB, bB, 0, 0);
#pragma unroll
        for (int kk = 0; kk < 4; kk++) {
            const int cur = kk & 1;
            if (kk < 3) load_frags(aB, bB, kk + 1, cur ^ 1);
#pragma unroll
            for (int mi = 0; mi < 4; mi++)
#pragma unroll
                for (int nj = 0; nj < 8; nj++)
                    mma16816(acc[mi][nj], fa[cur][mi], &fb[cur][nj >> 1][(nj & 1) * 2]);
        }
    }

    const int g   = lane >> 2;
    const int cc0 = (lane & 3) * 2;
#pragma unroll
    for (int mi = 0; mi < 4; mi++) {
#pragma unroll
        for (int nj = 0; nj < 8; nj++) {
            int row = m0 + m0w + mi * 16 + g;
            int col = o0 + n0w + nj * 8 + cc0;
            float2 v0 = make_float2(acc[mi][nj][0], acc[mi][nj][1]);
            float2 v1 = make_float2(acc[mi][nj][2], acc[mi][nj][3]);
            *reinterpret_cast<float2*>(&Cz[(size_t)row * ldc + col]) = v0;
            *reinterpret_cast<float2*>(&Cz[(size_t)(row + 8) * ldc + col]) = v1;
        }
    }
}

// ---------------------------------------------------------------------------
// Fixed-order slab reduction: out = sum_{z<NZ} S[z]   (float4 lanes)
// ---------------------------------------------------------------------------
template <int NZ>
__global__ void add_splits(const float* __restrict__ s, float* __restrict__ out,
                           size_t stride, int n4) {
    int i = blockIdx.x * blockDim.x + threadIdx.x;
    if (i >= n4) return;
    float4 a = reinterpret_cast<const float4*>(s)[i];
#pragma unroll
    for (int z = 1; z < NZ; z++) {
        float4 b = reinterpret_cast<const float4*>(s + z * stride)[i];
        a.x += b.x; a.y += b.y; a.z += b.z; a.w += b.w;
    }
    *reinterpret_cast<float4*>(out + (size_t)i * 4) = a;
}

// ---------------------------------------------------------------------------
// Launch
// ---------------------------------------------------------------------------
extern "C" void kernel_launch(void* const* d_in, const int* in_sizes, int n_in,
                              void* d_out, int out_size) {
    const float* x   = (const float*)d_in[0];
    const float* c1  = (const float*)d_in[1];
    const float* sb1 = (const float*)d_in[2];
    const float* sp1 = (const float*)d_in[3];
    const float* c2  = (const float*)d_in[4];
    const float* sb2 = (const float*)d_in[5];
    const float* sp2 = (const float*)d_in[6];
    float* out = (float*)d_out;

    const int D = D_MODEL, H = HIDDEN;
    const int N = in_sizes[0] / D;   // 4096

    void *pF, *pW1, *pW2, *pS, *pH;
    cudaGetSymbolAddress(&pF,  g_F);
    cudaGetSymbolAddress(&pW1, g_W1);
    cudaGetSymbolAddress(&pW2, g_W2);
    cudaGetSymbolAddress(&pS,  g_Sd);
    cudaGetSymbolAddress(&pH,  g_h);
    __nv_bfloat16* Fq  = (__nv_bfloat16*)pF;
    __nv_bfloat16* W1q = (__nv_bfloat16*)pW1;
    __nv_bfloat16* W2q = (__nv_bfloat16*)pW2;
    float* S  = (float*)pS;
    float* hb = (float*)pH;

    static bool attr_set = false;
    if (!attr_set) {
        cudaFuncSetAttribute(kan_gemm_mma,
                             cudaFuncAttributeMaxDynamicSharedMemorySize, SMEM_GEMM);
        attr_set = true;
    }

    // Fold + quantize weights
    prep_weights_q<<<dim3(H, D / 256), 256>>>(c1, sb1, sp1, W1q, D, H);
    prep_weights_q<<<dim3(D, H / 256), 256>>>(c2, sb2, sp2, W2q, H, D);

    // Layer 1: 216 logical chunks, split-K 4 -> 1024 CTAs x 54 chunks
    build_features_q<<<dim3(N, D / 256), 256>>>(x, Fq, D);
    kan_gemm_mma<<<dim3(H / 128, N / 128, 4), 128, SMEM_GEMM>>>(
        Fq, W1q, S, K1 / 64, (3 * (K1 / 64)) / 4, 2 * K1, H, (size_t)N * H);
    add_splits<4><<<(N * H / 4 + 255) / 256, 256>>>(S, hb, (size_t)N * H, N * H / 4);

    // Layer 2: 432 logical chunks, split-K 8 -> 1024 CTAs x 54 chunks
    build_features_q<<<dim3(N, H / 256), 256>>>(hb, Fq, H);
    kan_gemm_mma<<<dim3(D / 128, N / 128, 8), 128, SMEM_GEMM>>>(
        Fq, W2q, S, K2 / 64, (3 * (K2 / 64)) / 8, 2 * K2, D, (size_t)N * D);
    add_splits<8><<<(N * D / 4 + 255) / 256, 256>>>(S, out, (size_t)N * D, N * D / 4);
}

// round 11
// speedup vs baseline: 3.0462x; 1.0213x over previous
#include <cuda_runtime.h>
#include <cuda_bf16.h>
#include <math.h>
#include <stdint.h>

// ---------------------------------------------------------------------------
// KAN feedforward, bf16 3-term split (validated R5-R10, rel_err ~2.4e-5):
//   Logical A' = [Fhi | Fhi | Flo], B' = [Whi | Wlo | Whi]  (Keff = 3K)
//   Stored deduped: F = [Fhi | Flo], W = [Whi | Wlo]  (2K), chunk-remapped.
//   Split-K both GEMMs (validated balance: busiest SM 378 vs 432 chunks).
// R11: residual-kernel consolidation —
//   (a) prepW1 + prepW2 + featL1 merged into ONE launch (independent work)
//   (b) add_splits<4> fused into the L2 feature kernel (h never materialized)
//   8 launches -> 5. GEMMs untouched (they are at the rt=12 pipe floor).
// ---------------------------------------------------------------------------

#define D_MODEL 512
#define HIDDEN  1024
#define NFEAT   9
#define NTOK    4096
#define K1      (D_MODEL * NFEAT)   // 4608
#define K2      (HIDDEN  * NFEAT)   // 9216

__device__ __nv_bfloat16 g_F  [(size_t)NTOK * 2 * K2];     // 151 MB (both layers)
__device__ __nv_bfloat16 g_W1 [(size_t)HIDDEN * 2 * K1];   // 18.9 MB
__device__ __nv_bfloat16 g_W2 [(size_t)D_MODEL * 2 * K2];  // 18.9 MB
__device__ float g_Sd [(size_t)8 * NTOK * D_MODEL];        // 67 MB slabs (4xNH == 8xND)

// ---------------------------------------------------------------------------
// Helpers
// ---------------------------------------------------------------------------
__device__ __forceinline__ uint32_t smem_u32(const void* p) {
    uint32_t a;
    asm("{ .reg .u64 t; cvta.to.shared.u64 t, %1; cvt.u32.u64 %0, t; }"
        : "=r"(a) : "l"(p));
    return a;
}

__device__ __forceinline__ uint32_t lds_addr(uint32_t base, int row, int col16) {
    return base + row * 128 + ((col16 ^ (row & 7)) << 4);
}

#define CP_ASYNC16(sm, gm)                                                    \
    asm volatile("cp.async.cg.shared.global [%0], [%1], 16;"                  \
                 :: "r"(sm), "l"(gm) : "memory")
#define CP_COMMIT()  asm volatile("cp.async.commit_group;" ::: "memory")
#define CP_WAIT1()   asm volatile("cp.async.wait_group 1;" ::: "memory")

__device__ __forceinline__ void ldsm_x4(uint32_t r[4], uint32_t addr) {
    asm volatile("ldmatrix.sync.aligned.m8n8.x4.shared.b16 {%0,%1,%2,%3}, [%4];"
                 : "=r"(r[0]), "=r"(r[1]), "=r"(r[2]), "=r"(r[3]) : "r"(addr));
}

__device__ __forceinline__ void mma16816(float c[4], const uint32_t a[4],
                                         const uint32_t b[2]) {
    asm volatile(
        "mma.sync.aligned.m16n8k16.row.col.f32.bf16.bf16.f32 "
        "{%0,%1,%2,%3}, {%4,%5,%6,%7}, {%8,%9}, {%0,%1,%2,%3};"
        : "+f"(c[0]), "+f"(c[1]), "+f"(c[2]), "+f"(c[3])
        : "r"(a[0]), "r"(a[1]), "r"(a[2]), "r"(a[3]), "r"(b[0]), "r"(b[1]));
}

// ---------------------------------------------------------------------------
// Spline features (validated R3-R10)
// ---------------------------------------------------------------------------
__device__ __forceinline__ float knotf(int k) {
    return __fadd_rn(__fmul_rn((float)(k - 3), 0.4f), -1.0f);
}

__device__ __forceinline__ void kan_features(float x, float f[NFEAT]) {
    float sig = 1.0f / (1.0f + expf(-x));
    f[0] = x * sig;
#pragma unroll
    for (int g = 0; g < 8; g++) f[1 + g] = 0.0f;

    float u = (x - knotf(0)) * 2.5f;
    if (u > 16.0f) u = 16.0f;
    if (u < -16.0f) u = -16.0f;
    int j = (int)floorf(u);
    if (j < -1) j = -1;
    if (j > 11) j = 11;
    if (x < knotf(j))            j -= 1;
    else if (x >= knotf(j + 1))  j += 1;
    if (j < 0 || j > 10) return;

    float s  = (x - knotf(j)) * 2.5f;
    float s2 = s * s, s3 = s2 * s;
    float om = 1.0f - s;
    float w0 = om * om * om * (1.0f / 6.0f);
    float w1 = (3.0f * s3 - 6.0f * s2 + 4.0f) * (1.0f / 6.0f);
    float w2 = (-3.0f * s3 + 3.0f * s2 + 3.0f * s + 1.0f) * (1.0f / 6.0f);
    float w3 = s3 * (1.0f / 6.0f);
    float w[4] = {w0, w1, w2, w3};
    int g0 = j - 3;
#pragma unroll
    for (int r = 0; r < 4; r++) {
        int g = g0 + r;
        if (g >= 0 && g < 8) f[1 + g] = w[r];
    }
}

// Split f[] -> staged hi/lo smem, then coalesced copy-out of both runs.
__device__ __forceinline__ void split_stage_copyout(
    const float f[NFEAT], int t, __nv_bfloat16* sh, __nv_bfloat16* sl,
    __nv_bfloat16* dst_hi_base, int K) {
#pragma unroll
    for (int fi = 0; fi < NFEAT; fi++) {
        __nv_bfloat16 h = __float2bfloat16(f[fi]);
        sh[t * NFEAT + fi] = h;
        sl[t * NFEAT + fi] = __float2bfloat16(f[fi] - __bfloat162float(h));
    }
    __syncthreads();
    const uint32_t* s32h = reinterpret_cast<const uint32_t*>(sh);
    const uint32_t* s32l = reinterpret_cast<const uint32_t*>(sl);
    uint32_t* dh = reinterpret_cast<uint32_t*>(dst_hi_base);
    uint32_t* dl = reinterpret_cast<uint32_t*>(dst_hi_base + K);
    for (int p = t; p < 1152; p += 256) {
        dh[p] = s32h[p];
        dl[p] = s32l[p];
    }
}

// ---------------------------------------------------------------------------
// Merged pre-GEMM1 kernel: featL1 (8192 blocks) + prepW1 (2048) + prepW2 (2048)
// All blocks 256 threads; role decoded from blockIdx.x.
// ---------------------------------------------------------------------------
__global__ __launch_bounds__(256)
void pre_kernel(const float* __restrict__ X,
                const float* __restrict__ c1, const float* __restrict__ sb1,
                const float* __restrict__ sp1,
                const float* __restrict__ c2, const float* __restrict__ sb2,
                const float* __restrict__ sp2,
                __nv_bfloat16* __restrict__ F1q,
                __nv_bfloat16* __restrict__ W1q,
                __nv_bfloat16* __restrict__ W2q) {
    __shared__ __align__(16) __nv_bfloat16 sh[256 * NFEAT];
    __shared__ __align__(16) __nv_bfloat16 sl[256 * NFEAT];
    const int b = blockIdx.x;
    const int t = threadIdx.x;

    if (b < 2 * NTOK) {
        // --- featL1: n = b>>1, i0 = (b&1)*256, I = D_MODEL ---
        const int n  = b >> 1;
        const int i0 = (b & 1) << 8;
        const int K  = K1;
        float x = X[(size_t)n * D_MODEL + i0 + t];
        float f[NFEAT];
        kan_features(x, f);
        split_stage_copyout(f, t, sh, sl,
            F1q + (size_t)n * 2 * K + (size_t)i0 * NFEAT, K);
    } else if (b < 2 * NTOK + 2 * HIDDEN) {
        // --- prepW1: o = bb>>1, i0 = (bb&1)*256, I = D_MODEL, O = HIDDEN ---
        const int bb = b - 2 * NTOK;
        const int o  = bb >> 1;
        const int i0 = (bb & 1) << 8;
        const int K  = K1;
        const int i  = i0 + t;
        size_t io = (size_t)i * HIDDEN + o;
        float sp = sp1[io];
        float w[NFEAT];
        w[0] = sb1[io];
        const float* c = c1 + io * 8;
#pragma unroll
        for (int g = 0; g < 8; g++) w[1 + g] = c[g] * sp;
        split_stage_copyout(w, t, sh, sl,
            W1q + (size_t)o * 2 * K + (size_t)i0 * NFEAT, K);
    } else {
        // --- prepW2: o = bb>>2, i0 = (bb&3)*256, I = HIDDEN, O = D_MODEL ---
        const int bb = b - 2 * NTOK - 2 * HIDDEN;
        const int o  = bb >> 2;
        const int i0 = (bb & 3) << 8;
        const int K  = K2;
        const int i  = i0 + t;
        size_t io = (size_t)i * D_MODEL + o;
        float sp = sp2[io];
        float w[NFEAT];
        w[0] = sb2[io];
        const float* c = c2 + io * 8;
#pragma unroll
        for (int g = 0; g < 8; g++) w[1 + g] = c[g] * sp;
        split_stage_copyout(w, t, sh, sl,
            W2q + (size_t)o * 2 * K + (size_t)i0 * NFEAT, K);
    }
}

// ---------------------------------------------------------------------------
// Fused L2 features: h = sum of 4 slabs (fixed order, identical to R10's
// add_splits<4> + read), then features + split.  h never materialized.
// ---------------------------------------------------------------------------
__global__ __launch_bounds__(256)
void build_features_sum4(const float* __restrict__ S, size_t stride,
                         __nv_bfloat16* __restrict__ Fq) {
    __shared__ __align__(16) __nv_bfloat16 sh[256 * NFEAT];
    __shared__ __align__(16) __nv_bfloat16 sl[256 * NFEAT];
    const int n  = blockIdx.x;
    const int i0 = blockIdx.y << 8;
    const int t  = threadIdx.x;
    const int K  = K2;

    size_t idx = (size_t)n * HIDDEN + i0 + t;
    float x = S[idx];
#pragma unroll
    for (int z = 1; z < 4; z++) x += S[idx + (size_t)z * stride];

    float f[NFEAT];
    kan_features(x, f);
    split_stage_copyout(f, t, sh, sl,
        Fq + (size_t)n * 2 * K + (size_t)i0 * NFEAT, K);
}

// ---------------------------------------------------------------------------
// GEMM (R7/R10 mainloop, unchanged — at the rt=12 pipe floor):
//   S_z[m][o] = sum over this z's logical chunks of A'[m][.] * B'[o][.]
// ---------------------------------------------------------------------------
#define GEMM_BK      64
#define A_BYTES      (128 * 128)
#define STAGE_BYTES  (2 * A_BYTES)
#define SMEM_GEMM    (3 * STAGE_BYTES)

__global__ __launch_bounds__(128, 2)
void kan_gemm_mma(const __nv_bfloat16* __restrict__ A,
                  const __nv_bfloat16* __restrict__ B,
                  float* __restrict__ C,
                  int nK, int nchunks, int PK, int ldc, size_t csplit) {
    extern __shared__ __align__(1024) char smem_raw[];
    const uint32_t sb = smem_u32(smem_raw);

    const int tid  = threadIdx.x;
    const int lane = tid & 31;
    const int wid  = tid >> 5;
    const int m0w  = (wid & 1) * 64;
    const int n0w  = (wid >> 1) * 64;
    const int m0   = blockIdx.y * 128;
    const int o0   = blockIdx.x * 128;
    const int z0   = blockIdx.z * nchunks;
    float* Cz      = C + (size_t)blockIdx.z * csplit;

    const __nv_bfloat16* Arow = A + (size_t)m0 * PK;
    const __nv_bfloat16* Brow = B + (size_t)o0 * PK;

    const int r0   = tid >> 3;
    const int c16t = tid & 7;

    float acc[4][8][4];
#pragma unroll
    for (int mi = 0; mi < 4; mi++)
#pragma unroll
        for (int nj = 0; nj < 8; nj++)
#pragma unroll
            for (int e = 0; e < 4; e++) acc[mi][nj][e] = 0.0f;

    auto a_chunk = [&](int c) -> const __nv_bfloat16* {
        int p = (c < nK) ? c : c - nK;
        return Arow + (size_t)p * GEMM_BK;
    };
    auto b_chunk = [&](int c) -> const __nv_bfloat16* {
        int p = (c < 2 * nK) ? c : c - 2 * nK;
        return Brow + (size_t)p * GEMM_BK;
    };

    auto load_chunk = [&](int logical_c, int s) {
        const uint32_t aB = sb + s * STAGE_BYTES;
        const uint32_t bB = aB + A_BYTES;
        const __nv_bfloat16* Ap = a_chunk(logical_c) + c16t * 8;
        const __nv_bfloat16* Bp = b_chunk(logical_c) + c16t * 8;
#pragma unroll
        for (int it = 0; it < 8; it++) {
            int row = r0 + it * 16;
            CP_ASYNC16(lds_addr(aB, row, c16t), Ap + (size_t)row * PK);
        }
#pragma unroll
        for (int it = 0; it < 8; it++) {
            int row = r0 + it * 16;
            CP_ASYNC16(lds_addr(bB, row, c16t), Bp + (size_t)row * PK);
        }
    };

    uint32_t fa[2][4][4], fb[2][4][4];
    auto load_frags = [&](uint32_t aB, uint32_t bB, int kk, int buf) {
#pragma unroll
        for (int mi = 0; mi < 4; mi++)
            ldsm_x4(fa[buf][mi], lds_addr(aB, m0w + mi * 16 + (lane & 15),
                                          kk * 2 + (lane >> 4)));
#pragma unroll
        for (int nj2 = 0; nj2 < 4; nj2++) {
            int rowB = n0w + nj2 * 16 + ((lane >> 4) << 3) + (lane & 7);
            int colB = kk * 2 + ((lane >> 3) & 1);
            ldsm_x4(fb[buf][nj2], lds_addr(bB, rowB, colB));
        }
    };

    load_chunk(z0 + 0, 0); CP_COMMIT();
    load_chunk(z0 + 1, 1); CP_COMMIT();

    for (int cc = 0; cc < nchunks; cc++) {
        CP_WAIT1();
        __syncthreads();
        if (cc + 2 < nchunks) load_chunk(z0 + cc + 2, (cc + 2) % 3);
        CP_COMMIT();

        const uint32_t aB = sb + (cc % 3) * STAGE_BYTES;
        const uint32_t bB = aB + A_BYTES;
        load_frags(aB, bB, 0, 0);
#pragma unroll
        for (int kk = 0; kk < 4; kk++) {
            const int cur = kk & 1;
            if (kk < 3) load_frags(aB, bB, kk + 1, cur ^ 1);
#pragma unroll
            for (int mi = 0; mi < 4; mi++)
#pragma unroll
                for (int nj = 0; nj < 8; nj++)
                    mma16816(acc[mi][nj], fa[cur][mi], &fb[cur][nj >> 1][(nj & 1) * 2]);
        }
    }

    const int g   = lane >> 2;
    const int cc0 = (lane & 3) * 2;
#pragma unroll
    for (int mi = 0; mi < 4; mi++) {
#pragma unroll
        for (int nj = 0; nj < 8; nj++) {
            int row = m0 + m0w + mi * 16 + g;
            int col = o0 + n0w + nj * 8 + cc0;
            float2 v0 = make_float2(acc[mi][nj][0], acc[mi][nj][1]);
            float2 v1 = make_float2(acc[mi][nj][2], acc[mi][nj][3]);
            *reinterpret_cast<float2*>(&Cz[(size_t)row * ldc + col]) = v0;
            *reinterpret_cast<float2*>(&Cz[(size_t)(row + 8) * ldc + col]) = v1;
        }
    }
}

// ---------------------------------------------------------------------------
// Fixed-order slab reduction: out = sum_{z<8} S[z]   (float4 lanes)
// ---------------------------------------------------------------------------
__global__ void add_splits8(const float* __restrict__ s, float* __restrict__ out,
                            size_t stride, int n4) {
    int i = blockIdx.x * blockDim.x + threadIdx.x;
    if (i >= n4) return;
    float4 a = reinterpret_cast<const float4*>(s)[i];
#pragma unroll
    for (int z = 1; z < 8; z++) {
        float4 b = reinterpret_cast<const float4*>(s + z * stride)[i];
        a.x += b.x; a.y += b.y; a.z += b.z; a.w += b.w;
    }
    *reinterpret_cast<float4*>(out + (size_t)i * 4) = a;
}

// ---------------------------------------------------------------------------
// Launch (5 kernels)
// ---------------------------------------------------------------------------
extern "C" void kernel_launch(void* const* d_in, const int* in_sizes, int n_in,
                              void* d_out, int out_size) {
    const float* x   = (const float*)d_in[0];
    const float* c1  = (const float*)d_in[1];
    const float* sb1 = (const float*)d_in[2];
    const float* sp1 = (const float*)d_in[3];
    const float* c2  = (const float*)d_in[4];
    const float* sb2 = (const float*)d_in[5];
    const float* sp2 = (const float*)d_in[6];
    float* out = (float*)d_out;

    const int D = D_MODEL, H = HIDDEN;
    const int N = in_sizes[0] / D;   // 4096

    void *pF, *pW1, *pW2, *pS;
    cudaGetSymbolAddress(&pF,  g_F);
    cudaGetSymbolAddress(&pW1, g_W1);
    cudaGetSymbolAddress(&pW2, g_W2);
    cudaGetSymbolAddress(&pS,  g_Sd);
    __nv_bfloat16* Fq  = (__nv_bfloat16*)pF;
    __nv_bfloat16* W1q = (__nv_bfloat16*)pW1;
    __nv_bfloat16* W2q = (__nv_bfloat16*)pW2;
    float* S = (float*)pS;

    static bool attr_set = false;
    if (!attr_set) {
        cudaFuncSetAttribute(kan_gemm_mma,
                             cudaFuncAttributeMaxDynamicSharedMemorySize, SMEM_GEMM);
        attr_set = true;
    }

    // 1) All pre-GEMM1 work: featL1 + prepW1 + prepW2 (independent blocks)
    pre_kernel<<<2 * N + 2 * H + 4 * D, 256>>>(
        x, c1, sb1, sp1, c2, sb2, sp2, Fq, W1q, W2q);

    // 2) GEMM1: 216 logical chunks, split-K 4 -> 1024 CTAs x 54 chunks
    kan_gemm_mma<<<dim3(H / 128, N / 128, 4), 128, SMEM_GEMM>>>(
        Fq, W1q, S, K1 / 64, (3 * (K1 / 64)) / 4, 2 * K1, H, (size_t)N * H);

    // 3) L2 features fused with 4-slab sum (h never stored)
    build_features_sum4<<<dim3(N, H / 256), 256>>>(S, (size_t)N * H, Fq);

    // 4) GEMM2: 432 logical chunks, split-K 8 -> 1024 CTAs x 54 chunks
    kan_gemm_mma<<<dim3(D / 128, N / 128, 8), 128, SMEM_GEMM>>>(
        Fq, W2q, S, K2 / 64, (3 * (K2 / 64)) / 8, 2 * K2, D, (size_t)N * D);

    // 5) Final fixed-order reduction
    add_splits8<<<(N * D / 4 + 255) / 256, 256>>>(S, out, (size_t)N * D, N * D / 4);
}

// round 12
// speedup vs baseline: 3.0848x; 1.0127x over previous
#include <cuda_runtime.h>
#include <cuda_bf16.h>
#include <math.h>
#include <stdint.h>

// ---------------------------------------------------------------------------
// KAN feedforward, bf16 3-term split (validated R5-R11, rel_err 2.37e-5):
//   Logical A' = [Fhi | Fhi | Flo], B' = [Whi | Wlo | Whi]  (Keff = 3K)
//   Stored deduped: F = [Fhi | Flo], W = [Whi | Wlo]  (2K), chunk-remapped.
//   Split-K both GEMMs (critical-SM 378-chunk balance, at rt=12 pipe floor).
// R12: 128-bit vectorized smem->gmem copy-out in all staging kernels
//      (bit-identical data, 4x fewer STG). GEMMs untouched.
// ---------------------------------------------------------------------------

#define D_MODEL 512
#define HIDDEN  1024
#define NFEAT   9
#define NTOK    4096
#define K1      (D_MODEL * NFEAT)   // 4608
#define K2      (HIDDEN  * NFEAT)   // 9216

__device__ __nv_bfloat16 g_F  [(size_t)NTOK * 2 * K2];     // 151 MB (both layers)
__device__ __nv_bfloat16 g_W1 [(size_t)HIDDEN * 2 * K1];   // 18.9 MB
__device__ __nv_bfloat16 g_W2 [(size_t)D_MODEL * 2 * K2];  // 18.9 MB
__device__ float g_Sd [(size_t)8 * NTOK * D_MODEL];        // 67 MB slabs (4xNH == 8xND)

// ---------------------------------------------------------------------------
// Helpers
// ---------------------------------------------------------------------------
__device__ __forceinline__ uint32_t smem_u32(const void* p) {
    uint32_t a;
    asm("{ .reg .u64 t; cvta.to.shared.u64 t, %1; cvt.u32.u64 %0, t; }"
        : "=r"(a) : "l"(p));
    return a;
}

__device__ __forceinline__ uint32_t lds_addr(uint32_t base, int row, int col16) {
    return base + row * 128 + ((col16 ^ (row & 7)) << 4);
}

#define CP_ASYNC16(sm, gm)                                                    \
    asm volatile("cp.async.cg.shared.global [%0], [%1], 16;"                  \
                 :: "r"(sm), "l"(gm) : "memory")
#define CP_COMMIT()  asm volatile("cp.async.commit_group;" ::: "memory")
#define CP_WAIT1()   asm volatile("cp.async.wait_group 1;" ::: "memory")

__device__ __forceinline__ void ldsm_x4(uint32_t r[4], uint32_t addr) {
    asm volatile("ldmatrix.sync.aligned.m8n8.x4.shared.b16 {%0,%1,%2,%3}, [%4];"
                 : "=r"(r[0]), "=r"(r[1]), "=r"(r[2]), "=r"(r[3]) : "r"(addr));
}

__device__ __forceinline__ void mma16816(float c[4], const uint32_t a[4],
                                         const uint32_t b[2]) {
    asm volatile(
        "mma.sync.aligned.m16n8k16.row.col.f32.bf16.bf16.f32 "
        "{%0,%1,%2,%3}, {%4,%5,%6,%7}, {%8,%9}, {%0,%1,%2,%3};"
        : "+f"(c[0]), "+f"(c[1]), "+f"(c[2]), "+f"(c[3])
        : "r"(a[0]), "r"(a[1]), "r"(a[2]), "r"(a[3]), "r"(b[0]), "r"(b[1]));
}

// ---------------------------------------------------------------------------
// Spline features (validated R3-R11)
// ---------------------------------------------------------------------------
__device__ __forceinline__ float knotf(int k) {
    return __fadd_rn(__fmul_rn((float)(k - 3), 0.4f), -1.0f);
}

__device__ __forceinline__ void kan_features(float x, float f[NFEAT]) {
    float sig = 1.0f / (1.0f + expf(-x));
    f[0] = x * sig;
#pragma unroll
    for (int g = 0; g < 8; g++) f[1 + g] = 0.0f;

    float u = (x - knotf(0)) * 2.5f;
    if (u > 16.0f) u = 16.0f;
    if (u < -16.0f) u = -16.0f;
    int j = (int)floorf(u);
    if (j < -1) j = -1;
    if (j > 11) j = 11;
    if (x < knotf(j))            j -= 1;
    else if (x >= knotf(j + 1))  j += 1;
    if (j < 0 || j > 10) return;

    float s  = (x - knotf(j)) * 2.5f;
    float s2 = s * s, s3 = s2 * s;
    float om = 1.0f - s;
    float w0 = om * om * om * (1.0f / 6.0f);
    float w1 = (3.0f * s3 - 6.0f * s2 + 4.0f) * (1.0f / 6.0f);
    float w2 = (-3.0f * s3 + 3.0f * s2 + 3.0f * s + 1.0f) * (1.0f / 6.0f);
    float w3 = s3 * (1.0f / 6.0f);
    float w[4] = {w0, w1, w2, w3};
    int g0 = j - 3;
#pragma unroll
    for (int r = 0; r < 4; r++) {
        int g = g0 + r;
        if (g >= 0 && g < 8) f[1 + g] = w[r];
    }
}

// Split f[] -> staged hi/lo smem, then 128-bit coalesced copy-out of both runs.
// 256 threads * 9 bf16 = 4608 B per buffer = 288 uint4. Destinations are
// 16B-aligned (i0*9*2B is a multiple of 4608, K*2B multiple of 16).
__device__ __forceinline__ void split_stage_copyout(
    const float f[NFEAT], int t, __nv_bfloat16* sh, __nv_bfloat16* sl,
    __nv_bfloat16* dst_hi_base, int K) {
#pragma unroll
    for (int fi = 0; fi < NFEAT; fi++) {
        __nv_bfloat16 h = __float2bfloat16(f[fi]);
        sh[t * NFEAT + fi] = h;
        sl[t * NFEAT + fi] = __float2bfloat16(f[fi] - __bfloat162float(h));
    }
    __syncthreads();
    const uint4* s16h = reinterpret_cast<const uint4*>(sh);
    const uint4* s16l = reinterpret_cast<const uint4*>(sl);
    uint4* dh = reinterpret_cast<uint4*>(dst_hi_base);
    uint4* dl = reinterpret_cast<uint4*>(dst_hi_base + K);
    dh[t] = s16h[t];
    dl[t] = s16l[t];
    if (t < 32) {
        dh[256 + t] = s16h[256 + t];
        dl[256 + t] = s16l[256 + t];
    }
}

// ---------------------------------------------------------------------------
// Merged pre-GEMM1 kernel: featL1 (8192 blocks) + prepW1 (2048) + prepW2 (2048)
// ---------------------------------------------------------------------------
__global__ __launch_bounds__(256)
void pre_kernel(const float* __restrict__ X,
                const float* __restrict__ c1, const float* __restrict__ sb1,
                const float* __restrict__ sp1,
                const float* __restrict__ c2, const float* __restrict__ sb2,
                const float* __restrict__ sp2,
                __nv_bfloat16* __restrict__ F1q,
                __nv_bfloat16* __restrict__ W1q,
                __nv_bfloat16* __restrict__ W2q) {
    __shared__ __align__(16) __nv_bfloat16 sh[256 * NFEAT];
    __shared__ __align__(16) __nv_bfloat16 sl[256 * NFEAT];
    const int b = blockIdx.x;
    const int t = threadIdx.x;

    if (b < 2 * NTOK) {
        const int n  = b >> 1;
        const int i0 = (b & 1) << 8;
        float x = X[(size_t)n * D_MODEL + i0 + t];
        float f[NFEAT];
        kan_features(x, f);
        split_stage_copyout(f, t, sh, sl,
            F1q + (size_t)n * 2 * K1 + (size_t)i0 * NFEAT, K1);
    } else if (b < 2 * NTOK + 2 * HIDDEN) {
        const int bb = b - 2 * NTOK;
        const int o  = bb >> 1;
        const int i0 = (bb & 1) << 8;
        const int i  = i0 + t;
        size_t io = (size_t)i * HIDDEN + o;
        float sp = sp1[io];
        float w[NFEAT];
        w[0] = sb1[io];
        const float* c = c1 + io * 8;
#pragma unroll
        for (int g = 0; g < 8; g++) w[1 + g] = c[g] * sp;
        split_stage_copyout(w, t, sh, sl,
            W1q + (size_t)o * 2 * K1 + (size_t)i0 * NFEAT, K1);
    } else {
        const int bb = b - 2 * NTOK - 2 * HIDDEN;
        const int o  = bb >> 2;
        const int i0 = (bb & 3) << 8;
        const int i  = i0 + t;
        size_t io = (size_t)i * D_MODEL + o;
        float sp = sp2[io];
        float w[NFEAT];
        w[0] = sb2[io];
        const float* c = c2 + io * 8;
#pragma unroll
        for (int g = 0; g < 8; g++) w[1 + g] = c[g] * sp;
        split_stage_copyout(w, t, sh, sl,
            W2q + (size_t)o * 2 * K2 + (size_t)i0 * NFEAT, K2);
    }
}

// ---------------------------------------------------------------------------
// Fused L2 features: h = sum of 4 slabs (fixed order), features + split.
// ---------------------------------------------------------------------------
__global__ __launch_bounds__(256)
void build_features_sum4(const float* __restrict__ S, size_t stride,
                         __nv_bfloat16* __restrict__ Fq) {
    __shared__ __align__(16) __nv_bfloat16 sh[256 * NFEAT];
    __shared__ __align__(16) __nv_bfloat16 sl[256 * NFEAT];
    const int n  = blockIdx.x;
    const int i0 = blockIdx.y << 8;
    const int t  = threadIdx.x;

    size_t idx = (size_t)n * HIDDEN + i0 + t;
    float x = S[idx];
#pragma unroll
    for (int z = 1; z < 4; z++) x += S[idx + (size_t)z * stride];

    float f[NFEAT];
    kan_features(x, f);
    split_stage_copyout(f, t, sh, sl,
        Fq + (size_t)n * 2 * K2 + (size_t)i0 * NFEAT, K2);
}

// ---------------------------------------------------------------------------
// GEMM (R7/R10 mainloop, unchanged — at the rt=12 pipe floor)
// ---------------------------------------------------------------------------
#define GEMM_BK      64
#define A_BYTES      (128 * 128)
#define STAGE_BYTES  (2 * A_BYTES)
#define SMEM_GEMM    (3 * STAGE_BYTES)

__global__ __launch_bounds__(128, 2)
void kan_gemm_mma(const __nv_bfloat16* __restrict__ A,
                  const __nv_bfloat16* __restrict__ B,
                  float* __restrict__ C,
                  int nK, int nchunks, int PK, int ldc, size_t csplit) {
    extern __shared__ __align__(1024) char smem_raw[];
    const uint32_t sb = smem_u32(smem_raw);

    const int tid  = threadIdx.x;
    const int lane = tid & 31;
    const int wid  = tid >> 5;
    const int m0w  = (wid & 1) * 64;
    const int n0w  = (wid >> 1) * 64;
    const int m0   = blockIdx.y * 128;
    const int o0   = blockIdx.x * 128;
    const int z0   = blockIdx.z * nchunks;
    float* Cz      = C + (size_t)blockIdx.z * csplit;

    const __nv_bfloat16* Arow = A + (size_t)m0 * PK;
    const __nv_bfloat16* Brow = B + (size_t)o0 * PK;

    const int r0   = tid >> 3;
    const int c16t = tid & 7;

    float acc[4][8][4];
#pragma unroll
    for (int mi = 0; mi < 4; mi++)
#pragma unroll
        for (int nj = 0; nj < 8; nj++)
#pragma unroll
            for (int e = 0; e < 4; e++) acc[mi][nj][e] = 0.0f;

    auto a_chunk = [&](int c) -> const __nv_bfloat16* {
        int p = (c < nK) ? c : c - nK;
        return Arow + (size_t)p * GEMM_BK;
    };
    auto b_chunk = [&](int c) -> const __nv_bfloat16* {
        int p = (c < 2 * nK) ? c : c - 2 * nK;
        return Brow + (size_t)p * GEMM_BK;
    };

    auto load_chunk = [&](int logical_c, int s) {
        const uint32_t aB = sb + s * STAGE_BYTES;
        const uint32_t bB = aB + A_BYTES;
        const __nv_bfloat16* Ap = a_chunk(logical_c) + c16t * 8;
        const __nv_bfloat16* Bp = b_chunk(logical_c) + c16t * 8;
#pragma unroll
        for (int it = 0; it < 8; it++) {
            int row = r0 + it * 16;
            CP_ASYNC16(lds_addr(aB, row, c16t), Ap + (size_t)row * PK);
        }
#pragma unroll
        for (int it = 0; it < 8; it++) {
            int row = r0 + it * 16;
            CP_ASYNC16(lds_addr(bB, row, c16t), Bp + (size_t)row * PK);
        }
    };

    uint32_t fa[2][4][4], fb[2][4][4];
    auto load_frags = [&](uint32_t aB, uint32_t bB, int kk, int buf) {
#pragma unroll
        for (int mi = 0; mi < 4; mi++)
            ldsm_x4(fa[buf][mi], lds_addr(aB, m0w + mi * 16 + (lane & 15),
                                          kk * 2 + (lane >> 4)));
#pragma unroll
        for (int nj2 = 0; nj2 < 4; nj2++) {
            int rowB = n0w + nj2 * 16 + ((lane >> 4) << 3) + (lane & 7);
            int colB = kk * 2 + ((lane >> 3) & 1);
            ldsm_x4(fb[buf][nj2], lds_addr(bB, rowB, colB));
        }
    };

    load_chunk(z0 + 0, 0); CP_COMMIT();
    load_chunk(z0 + 1, 1); CP_COMMIT();

    for (int cc = 0; cc < nchunks; cc++) {
        CP_WAIT1();
        __syncthreads();
        if (cc + 2 < nchunks) load_chunk(z0 + cc + 2, (cc + 2) % 3);
        CP_COMMIT();

        const uint32_t aB = sb + (cc % 3) * STAGE_BYTES;
        const uint32_t bB = aB + A_BYTES;
        load_frags(aB, bB, 0, 0);
#pragma unroll
        for (int kk = 0; kk < 4; kk++) {
            const int cur = kk & 1;
            if (kk < 3) load_frags(aB, bB, kk + 1, cur ^ 1);
#pragma unroll
            for (int mi = 0; mi < 4; mi++)
#pragma unroll
                for (int nj = 0; nj < 8; nj++)
                    mma16816(acc[mi][nj], fa[cur][mi], &fb[cur][nj >> 1][(nj & 1) * 2]);
        }
    }

    const int g   = lane >> 2;
    const int cc0 = (lane & 3) * 2;
#pragma unroll
    for (int mi = 0; mi < 4; mi++) {
#pragma unroll
        for (int nj = 0; nj < 8; nj++) {
            int row = m0 + m0w + mi * 16 + g;
            int col = o0 + n0w + nj * 8 + cc0;
            float2 v0 = make_float2(acc[mi][nj][0], acc[mi][nj][1]);
            float2 v1 = make_float2(acc[mi][nj][2], acc[mi][nj][3]);
            *reinterpret_cast<float2*>(&Cz[(size_t)row * ldc + col]) = v0;
            *reinterpret_cast<float2*>(&Cz[(size_t)(row + 8) * ldc + col]) = v1;
        }
    }
}

// ---------------------------------------------------------------------------
// Fixed-order slab reduction: out = sum_{z<8} S[z]   (float4 lanes)
// ---------------------------------------------------------------------------
__global__ void add_splits8(const float* __restrict__ s, float* __restrict__ out,
                            size_t stride, int n4) {
    int i = blockIdx.x * blockDim.x + threadIdx.x;
    if (i >= n4) return;
    float4 a = reinterpret_cast<const float4*>(s)[i];
#pragma unroll
    for (int z = 1; z < 8; z++) {
        float4 b = reinterpret_cast<const float4*>(s + z * stride)[i];
        a.x += b.x; a.y += b.y; a.z += b.z; a.w += b.w;
    }
    *reinterpret_cast<float4*>(out + (size_t)i * 4) = a;
}

// ---------------------------------------------------------------------------
// Launch (5 kernels)
// ---------------------------------------------------------------------------
extern "C" void kernel_launch(void* const* d_in, const int* in_sizes, int n_in,
                              void* d_out, int out_size) {
    const float* x   = (const float*)d_in[0];
    const float* c1  = (const float*)d_in[1];
    const float* sb1 = (const float*)d_in[2];
    const float* sp1 = (const float*)d_in[3];
    const float* c2  = (const float*)d_in[4];
    const float* sb2 = (const float*)d_in[5];
    const float* sp2 = (const float*)d_in[6];
    float* out = (float*)d_out;

    const int D = D_MODEL, H = HIDDEN;
    const int N = in_sizes[0] / D;   // 4096

    void *pF, *pW1, *pW2, *pS;
    cudaGetSymbolAddress(&pF,  g_F);
    cudaGetSymbolAddress(&pW1, g_W1);
    cudaGetSymbolAddress(&pW2, g_W2);
    cudaGetSymbolAddress(&pS,  g_Sd);
    __nv_bfloat16* Fq  = (__nv_bfloat16*)pF;
    __nv_bfloat16* W1q = (__nv_bfloat16*)pW1;
    __nv_bfloat16* W2q = (__nv_bfloat16*)pW2;
    float* S = (float*)pS;

    static bool attr_set = false;
    if (!attr_set) {
        cudaFuncSetAttribute(kan_gemm_mma,
                             cudaFuncAttributeMaxDynamicSharedMemorySize, SMEM_GEMM);
        attr_set = true;
    }

    // 1) All pre-GEMM1 work: featL1 + prepW1 + prepW2
    pre_kernel<<<2 * N + 2 * H + 4 * D, 256>>>(
        x, c1, sb1, sp1, c2, sb2, sp2, Fq, W1q, W2q);

    // 2) GEMM1: 216 logical chunks, split-K 4 -> 1024 CTAs x 54 chunks
    kan_gemm_mma<<<dim3(H / 128, N / 128, 4), 128, SMEM_GEMM>>>(
        Fq, W1q, S, K1 / 64, (3 * (K1 / 64)) / 4, 2 * K1, H, (size_t)N * H);

    // 3) L2 features fused with 4-slab sum (h never stored)
    build_features_sum4<<<dim3(N, H / 256), 256>>>(S, (size_t)N * H, Fq);

    // 4) GEMM2: 432 logical chunks, split-K 8 -> 1024 CTAs x 54 chunks
    kan_gemm_mma<<<dim3(D / 128, N / 128, 8), 128, SMEM_GEMM>>>(
        Fq, W2q, S, K2 / 64, (3 * (K2 / 64)) / 8, 2 * K2, D, (size_t)N * D);

    // 5) Final fixed-order reduction
    add_splits8<<<(N * D / 4 + 255) / 256, 256>>>(S, out, (size_t)N * D, N * D / 4);
}

// round 13
// speedup vs baseline: 4.2580x; 1.3803x over previous
#include <cuda_runtime.h>
#include <cuda_fp16.h>
#include <math.h>
#include <stdint.h>

// ---------------------------------------------------------------------------
// KAN feedforward, fp16 2-product split with slab reweighting (R13):
//   A1 = a_hi,  A2 = fp16(a_hi/c + c*a_lo),  same for B,  c = 16.
//   S1 = A1.B1 = S_hihi;  S2 = A2.B2 = S_hihi/c^2 + S_cross + c^2 S_lolo + eps
//   out = (1 - 1/c^2) * S1 + S2   (exact cancellation via separate slabs)
//   Keff = 2K (vs 3K in R12)  ->  GEMM work cut 33%.
// Spline/feature math identical to R3-R12. Split-K slab boundaries align
// with the term boundary, so reweighting folds into existing combiners.
// ---------------------------------------------------------------------------

#define D_MODEL 512
#define HIDDEN  1024
#define NFEAT   9
#define NTOK    4096
#define K1      (D_MODEL * NFEAT)   // 4608
#define K2      (HIDDEN  * NFEAT)   // 9216
#define CSPLIT  16.0f
#define W1FACT  0.99609375f         // 1 - 1/256, exact in fp32

__device__ __half g_F  [(size_t)NTOK * 2 * K2];     // 151 MB (both layers)
__device__ __half g_W1 [(size_t)HIDDEN * 2 * K1];   // 18.9 MB
__device__ __half g_W2 [(size_t)D_MODEL * 2 * K2];  // 18.9 MB
__device__ float  g_Sd [(size_t)8 * NTOK * D_MODEL];// 67 MB slabs (4xNH == 8xND)

// ---------------------------------------------------------------------------
// Helpers
// ---------------------------------------------------------------------------
__device__ __forceinline__ uint32_t smem_u32(const void* p) {
    uint32_t a;
    asm("{ .reg .u64 t; cvta.to.shared.u64 t, %1; cvt.u32.u64 %0, t; }"
        : "=r"(a) : "l"(p));
    return a;
}

__device__ __forceinline__ uint32_t lds_addr(uint32_t base, int row, int col16) {
    return base + row * 128 + ((col16 ^ (row & 7)) << 4);
}

#define CP_ASYNC16(sm, gm)                                                    \
    asm volatile("cp.async.cg.shared.global [%0], [%1], 16;"                  \
                 :: "r"(sm), "l"(gm) : "memory")
#define CP_COMMIT()  asm volatile("cp.async.commit_group;" ::: "memory")
#define CP_WAIT1()   asm volatile("cp.async.wait_group 1;" ::: "memory")

__device__ __forceinline__ void ldsm_x4(uint32_t r[4], uint32_t addr) {
    asm volatile("ldmatrix.sync.aligned.m8n8.x4.shared.b16 {%0,%1,%2,%3}, [%4];"
                 : "=r"(r[0]), "=r"(r[1]), "=r"(r[2]), "=r"(r[3]) : "r"(addr));
}

__device__ __forceinline__ void mma16816(float c[4], const uint32_t a[4],
                                         const uint32_t b[2]) {
    asm volatile(
        "mma.sync.aligned.m16n8k16.row.col.f32.f16.f16.f32 "
        "{%0,%1,%2,%3}, {%4,%5,%6,%7}, {%8,%9}, {%0,%1,%2,%3};"
        : "+f"(c[0]), "+f"(c[1]), "+f"(c[2]), "+f"(c[3])
        : "r"(a[0]), "r"(a[1]), "r"(a[2]), "r"(a[3]), "r"(b[0]), "r"(b[1]));
}

// ---------------------------------------------------------------------------
// Spline features (validated R3-R12)
// ---------------------------------------------------------------------------
__device__ __forceinline__ float knotf(int k) {
    return __fadd_rn(__fmul_rn((float)(k - 3), 0.4f), -1.0f);
}

__device__ __forceinline__ void kan_features(float x, float f[NFEAT]) {
    float sig = 1.0f / (1.0f + expf(-x));
    f[0] = x * sig;
#pragma unroll
    for (int g = 0; g < 8; g++) f[1 + g] = 0.0f;

    float u = (x - knotf(0)) * 2.5f;
    if (u > 16.0f) u = 16.0f;
    if (u < -16.0f) u = -16.0f;
    int j = (int)floorf(u);
    if (j < -1) j = -1;
    if (j > 11) j = 11;
    if (x < knotf(j))            j -= 1;
    else if (x >= knotf(j + 1))  j += 1;
    if (j < 0 || j > 10) return;

    float s  = (x - knotf(j)) * 2.5f;
    float s2 = s * s, s3 = s2 * s;
    float om = 1.0f - s;
    float w0 = om * om * om * (1.0f / 6.0f);
    float w1 = (3.0f * s3 - 6.0f * s2 + 4.0f) * (1.0f / 6.0f);
    float w2 = (-3.0f * s3 + 3.0f * s2 + 3.0f * s + 1.0f) * (1.0f / 6.0f);
    float w3 = s3 * (1.0f / 6.0f);
    float w[4] = {w0, w1, w2, w3};
    int g0 = j - 3;
#pragma unroll
    for (int r = 0; r < 4; r++) {
        int g = g0 + r;
        if (g >= 0 && g < 8) f[1 + g] = w[r];
    }
}

// v -> (hi, X2 = fp16(hi/c + c*lo)),  stage in smem, 128-bit copy-out of
// both contiguous runs ([hi-run | X2-run], X2-run at +K elements).
__device__ __forceinline__ void split_stage_copyout(
    const float f[NFEAT], int t, __half* sh, __half* s2,
    __half* dst_hi_base, int K) {
#pragma unroll
    for (int fi = 0; fi < NFEAT; fi++) {
        __half h = __float2half(f[fi]);
        float hf = __half2float(h);
        float lo = f[fi] - hf;
        sh[t * NFEAT + fi] = h;
        s2[t * NFEAT + fi] = __float2half(hf * (1.0f / CSPLIT) + lo * CSPLIT);
    }
    __syncthreads();
    const uint4* v1 = reinterpret_cast<const uint4*>(sh);
    const uint4* v2 = reinterpret_cast<const uint4*>(s2);
    uint4* dh = reinterpret_cast<uint4*>(dst_hi_base);
    uint4* d2 = reinterpret_cast<uint4*>(dst_hi_base + K);
    dh[t] = v1[t];
    d2[t] = v2[t];
    if (t < 32) {
        dh[256 + t] = v1[256 + t];
        d2[256 + t] = v2[256 + t];
    }
}

// ---------------------------------------------------------------------------
// Merged pre-GEMM1 kernel: featL1 (8192 blocks) + prepW1 (2048) + prepW2 (2048)
// ---------------------------------------------------------------------------
__global__ __launch_bounds__(256)
void pre_kernel(const float* __restrict__ X,
                const float* __restrict__ c1, const float* __restrict__ sb1,
                const float* __restrict__ sp1,
                const float* __restrict__ c2, const float* __restrict__ sb2,
                const float* __restrict__ sp2,
                __half* __restrict__ F1q,
                __half* __restrict__ W1q,
                __half* __restrict__ W2q) {
    __shared__ __align__(16) __half sh[256 * NFEAT];
    __shared__ __align__(16) __half s2[256 * NFEAT];
    const int b = blockIdx.x;
    const int t = threadIdx.x;

    if (b < 2 * NTOK) {
        const int n  = b >> 1;
        const int i0 = (b & 1) << 8;
        float x = X[(size_t)n * D_MODEL + i0 + t];
        float f[NFEAT];
        kan_features(x, f);
        split_stage_copyout(f, t, sh, s2,
            F1q + (size_t)n * 2 * K1 + (size_t)i0 * NFEAT, K1);
    } else if (b < 2 * NTOK + 2 * HIDDEN) {
        const int bb = b - 2 * NTOK;
        const int o  = bb >> 1;
        const int i0 = (bb & 1) << 8;
        const int i  = i0 + t;
        size_t io = (size_t)i * HIDDEN + o;
        float sp = sp1[io];
        float w[NFEAT];
        w[0] = sb1[io];
        const float* c = c1 + io * 8;
#pragma unroll
        for (int g = 0; g < 8; g++) w[1 + g] = c[g] * sp;
        split_stage_copyout(w, t, sh, s2,
            W1q + (size_t)o * 2 * K1 + (size_t)i0 * NFEAT, K1);
    } else {
        const int bb = b - 2 * NTOK - 2 * HIDDEN;
        const int o  = bb >> 2;
        const int i0 = (bb & 3) << 8;
        const int i  = i0 + t;
        size_t io = (size_t)i * D_MODEL + o;
        float sp = sp2[io];
        float w[NFEAT];
        w[0] = sb2[io];
        const float* c = c2 + io * 8;
#pragma unroll
        for (int g = 0; g < 8; g++) w[1 + g] = c[g] * sp;
        split_stage_copyout(w, t, sh, s2,
            W2q + (size_t)o * 2 * K2 + (size_t)i0 * NFEAT, K2);
    }
}

// ---------------------------------------------------------------------------
// Fused L2 features: h = (S0+S1)*(1-1/c^2) + (S2+S3)   (term reweighting),
// then features + split.  h never materialized.
// ---------------------------------------------------------------------------
__global__ __launch_bounds__(256)
void build_features_sum4(const float* __restrict__ S, size_t stride,
                         __half* __restrict__ Fq) {
    __shared__ __align__(16) __half sh[256 * NFEAT];
    __shared__ __align__(16) __half s2[256 * NFEAT];
    const int n  = blockIdx.x;
    const int i0 = blockIdx.y << 8;
    const int t  = threadIdx.x;

    size_t idx = (size_t)n * HIDDEN + i0 + t;
    float x = (S[idx] + S[idx + stride]) * W1FACT
            + (S[idx + 2 * stride] + S[idx + 3 * stride]);

    float f[NFEAT];
    kan_features(x, f);
    split_stage_copyout(f, t, sh, s2,
        Fq + (size_t)n * 2 * K2 + (size_t)i0 * NFEAT, K2);
}

// ---------------------------------------------------------------------------
// GEMM (R7-R12 mainloop; straight chunk indexing — physical == logical):
//   S_z[m][o] = sum over this z's chunks of A[m][.] * B[o][.]
// ---------------------------------------------------------------------------
#define GEMM_BK      64
#define A_BYTES      (128 * 128)
#define STAGE_BYTES  (2 * A_BYTES)
#define SMEM_GEMM    (3 * STAGE_BYTES)

__global__ __launch_bounds__(128, 2)
void kan_gemm_mma(const __half* __restrict__ A,
                  const __half* __restrict__ B,
                  float* __restrict__ C,
                  int nchunks, int PK, int ldc, size_t csplit) {
    extern __shared__ __align__(1024) char smem_raw[];
    const uint32_t sb = smem_u32(smem_raw);

    const int tid  = threadIdx.x;
    const int lane = tid & 31;
    const int wid  = tid >> 5;
    const int m0w  = (wid & 1) * 64;
    const int n0w  = (wid >> 1) * 64;
    const int m0   = blockIdx.y * 128;
    const int o0   = blockIdx.x * 128;
    const int z0   = blockIdx.z * nchunks;
    float* Cz      = C + (size_t)blockIdx.z * csplit;

    const __half* Arow = A + (size_t)m0 * PK;
    const __half* Brow = B + (size_t)o0 * PK;

    const int r0   = tid >> 3;
    const int c16t = tid & 7;

    float acc[4][8][4];
#pragma unroll
    for (int mi = 0; mi < 4; mi++)
#pragma unroll
        for (int nj = 0; nj < 8; nj++)
#pragma unroll
            for (int e = 0; e < 4; e++) acc[mi][nj][e] = 0.0f;

    auto load_chunk = [&](int c, int s) {
        const uint32_t aB = sb + s * STAGE_BYTES;
        const uint32_t bB = aB + A_BYTES;
        const __half* Ap = Arow + (size_t)c * GEMM_BK + c16t * 8;
        const __half* Bp = Brow + (size_t)c * GEMM_BK + c16t * 8;
#pragma unroll
        for (int it = 0; it < 8; it++) {
            int row = r0 + it * 16;
            CP_ASYNC16(lds_addr(aB, row, c16t), Ap + (size_t)row * PK);
        }
#pragma unroll
        for (int it = 0; it < 8; it++) {
            int row = r0 + it * 16;
            CP_ASYNC16(lds_addr(bB, row, c16t), Bp + (size_t)row * PK);
        }
    };

    uint32_t fa[2][4][4], fb[2][4][4];
    auto load_frags = [&](uint32_t aB, uint32_t bB, int kk, int buf) {
#pragma unroll
        for (int mi = 0; mi < 4; mi++)
            ldsm_x4(fa[buf][mi], lds_addr(aB, m0w + mi * 16 + (lane & 15),
                                          kk * 2 + (lane >> 4)));
#pragma unroll
        for (int nj2 = 0; nj2 < 4; nj2++) {
            int rowB = n0w + nj2 * 16 + ((lane >> 4) << 3) + (lane & 7);
            int colB = kk * 2 + ((lane >> 3) & 1);
            ldsm_x4(fb[buf][nj2], lds_addr(bB, rowB, colB));
        }
    };

    load_chunk(z0 + 0, 0); CP_COMMIT();
    load_chunk(z0 + 1, 1); CP_COMMIT();

    for (int cc = 0; cc < nchunks; cc++) {
        CP_WAIT1();
        __syncthreads();
        if (cc + 2 < nchunks) load_chunk(z0 + cc + 2, (cc + 2) % 3);
        CP_COMMIT();

        const uint32_t aB = sb + (cc % 3) * STAGE_BYTES;
        const uint32_t bB = aB + A_BYTES;
        load_frags(aB, bB, 0, 0);
#pragma unroll
        for (int kk = 0; kk < 4; kk++) {
            const int cur = kk & 1;
            if (kk < 3) load_frags(aB, bB, kk + 1, cur ^ 1);
#pragma unroll
            for (int mi = 0; mi < 4; mi++)
#pragma unroll
                for (int nj = 0; nj < 8; nj++)
                    mma16816(acc[mi][nj], fa[cur][mi], &fb[cur][nj >> 1][(nj & 1) * 2]);
        }
    }

    const int g   = lane >> 2;
    const int cc0 = (lane & 3) * 2;
#pragma unroll
    for (int mi = 0; mi < 4; mi++) {
#pragma unroll
        for (int nj = 0; nj < 8; nj++) {
            int row = m0 + m0w + mi * 16 + g;
            int col = o0 + n0w + nj * 8 + cc0;
            float2 v0 = make_float2(acc[mi][nj][0], acc[mi][nj][1]);
            float2 v1 = make_float2(acc[mi][nj][2], acc[mi][nj][3]);
            *reinterpret_cast<float2*>(&Cz[(size_t)row * ldc + col]) = v0;
            *reinterpret_cast<float2*>(&Cz[(size_t)(row + 8) * ldc + col]) = v1;
        }
    }
}

// ---------------------------------------------------------------------------
// Final reduction with term reweighting:
//   out = (S0+S1+S2+S3)*(1-1/c^2) + (S4+S5+S6+S7)
// ---------------------------------------------------------------------------
__global__ void add_splits8w(const float* __restrict__ s, float* __restrict__ out,
                             size_t stride, int n4) {
    int i = blockIdx.x * blockDim.x + threadIdx.x;
    if (i >= n4) return;
    float4 a = reinterpret_cast<const float4*>(s)[i];
#pragma unroll
    for (int z = 1; z < 4; z++) {
        float4 b = reinterpret_cast<const float4*>(s + z * stride)[i];
        a.x += b.x; a.y += b.y; a.z += b.z; a.w += b.w;
    }
    a.x *= W1FACT; a.y *= W1FACT; a.z *= W1FACT; a.w *= W1FACT;
#pragma unroll
    for (int z = 4; z < 8; z++) {
        float4 b = reinterpret_cast<const float4*>(s + z * stride)[i];
        a.x += b.x; a.y += b.y; a.z += b.z; a.w += b.w;
    }
    *reinterpret_cast<float4*>(out + (size_t)i * 4) = a;
}

// ---------------------------------------------------------------------------
// Launch (5 kernels)
// ---------------------------------------------------------------------------
extern "C" void kernel_launch(void* const* d_in, const int* in_sizes, int n_in,
                              void* d_out, int out_size) {
    const float* x   = (const float*)d_in[0];
    const float* c1  = (const float*)d_in[1];
    const float* sb1 = (const float*)d_in[2];
    const float* sp1 = (const float*)d_in[3];
    const float* c2  = (const float*)d_in[4];
    const float* sb2 = (const float*)d_in[5];
    const float* sp2 = (const float*)d_in[6];
    float* out = (float*)d_out;

    const int D = D_MODEL, H = HIDDEN;
    const int N = in_sizes[0] / D;   // 4096

    void *pF, *pW1, *pW2, *pS;
    cudaGetSymbolAddress(&pF,  g_F);
    cudaGetSymbolAddress(&pW1, g_W1);
    cudaGetSymbolAddress(&pW2, g_W2);
    cudaGetSymbolAddress(&pS,  g_Sd);
    __half* Fq  = (__half*)pF;
    __half* W1q = (__half*)pW1;
    __half* W2q = (__half*)pW2;
    float* S = (float*)pS;

    static bool attr_set = false;
    if (!attr_set) {
        cudaFuncSetAttribute(kan_gemm_mma,
                             cudaFuncAttributeMaxDynamicSharedMemorySize, SMEM_GEMM);
        attr_set = true;
    }

    // 1) All pre-GEMM1 work: featL1 + prepW1 + prepW2
    pre_kernel<<<2 * N + 2 * H + 4 * D, 256>>>(
        x, c1, sb1, sp1, c2, sb2, sp2, Fq, W1q, W2q);

    // 2) GEMM1: 144 chunks (2*K1/64), split-K 4 -> 1024 CTAs x 36 chunks.
    //    z=0,1 cover hi.hi chunks [0,72); z=2,3 cover cross chunks [72,144).
    kan_gemm_mma<<<dim3(H / 128, N / 128, 4), 128, SMEM_GEMM>>>(
        Fq, W1q, S, (2 * K1 / 64) / 4, 2 * K1, H, (size_t)N * H);

    // 3) L2 features fused with reweighted 4-slab sum (h never stored)
    build_features_sum4<<<dim3(N, H / 256), 256>>>(S, (size_t)N * H, Fq);

    // 4) GEMM2: 288 chunks (2*K2/64), split-K 8 -> 1024 CTAs x 36 chunks.
    //    z=0..3 hi.hi [0,144); z=4..7 cross [144,288).
    kan_gemm_mma<<<dim3(D / 128, N / 128, 8), 128, SMEM_GEMM>>>(
        Fq, W2q, S, (2 * K2 / 64) / 8, 2 * K2, D, (size_t)N * D);

    // 5) Final reweighted fixed-order reduction
    add_splits8w<<<(N * D / 4 + 255) / 256, 256>>>(S, out, (size_t)N * D, N * D / 4);
}